// round 8
// baseline (speedup 1.0000x reference)
#include <cuda_runtime.h>
#include <cuda_bf16.h>
#include <mma.h>
#include <cstdint>

using namespace nvcuda;

// ---------------- geometry ----------------
#define GD0 27
#define GH0 127
#define GW0 127
#define NVOX (GD0*GH0*GW0)        // 435483
#define GD1 14
#define GH1 64
#define GW1 64
#define NC1 (GD1*GH1*GW1)         // 57344
#define GD2 7
#define GH2 32
#define GW2 32
#define NC2 (GD2*GH2*GW2)         // 7168
#define FS 64                     // fine buffer channel stride
#define CS 96                     // coarse buffer channel stride

// ---------------- static scratch (zero-init at module load; inactive voxels
// never written; validated R4-R6: rel_err identical without memsets) ----
__device__ float g_fineA[(size_t)NVOX * FS];
__device__ float g_fineB[(size_t)NVOX * FS];
__device__ float g_cA[NC1 * CS];
__device__ float g_cB[NC1 * CS];
__device__ float g_c2[NC2 * CS];
__device__ float g_mask[NC1];
__device__ float g_wi1[8 * 64 * 96];
__device__ float g_wi0[27 * 32 * 64];
// bf16 hi/lo weight images for wmma layers, ORIGINAL [tap][ci][co] layout
__device__ __align__(256) __nv_bfloat16 g_b4hi[27 * 64 * 96];
__device__ __align__(256) __nv_bfloat16 g_b4lo[27 * 64 * 96];
__device__ __align__(256) __nv_bfloat16 g_b5hi[27 * 96 * 96];
__device__ __align__(256) __nv_bfloat16 g_b5lo[27 * 96 * 96];

// ---------------- helpers ----------------
__device__ __forceinline__ void packpair(float x, float y, uint32_t& h, uint32_t& l) {
    __nv_bfloat16 hx = __float2bfloat16(x), hy = __float2bfloat16(y);
    __nv_bfloat16 lx = __float2bfloat16(x - __bfloat162float(hx));
    __nv_bfloat16 ly = __float2bfloat16(y - __bfloat162float(hy));
    __nv_bfloat162 hh; hh.x = hx; hh.y = hy;
    __nv_bfloat162 ll; ll.x = lx; ll.y = ly;
    h = *reinterpret_cast<uint32_t*>(&hh);
    l = *reinterpret_cast<uint32_t*>(&ll);
}

// weights -> bf16 hi/lo, same layout
__global__ void bprep_kernel(const float* __restrict__ W, __nv_bfloat16* __restrict__ hi,
                             __nv_bfloat16* __restrict__ lo, int tot) {
    int i = blockIdx.x * blockDim.x + threadIdx.x;
    if (i >= tot) return;
    float v = W[i];
    __nv_bfloat16 h = __float2bfloat16(v);
    hi[i] = h;
    lo[i] = __float2bfloat16(v - __bfloat162float(h));
}

// ---------------- wmma coarse conv (k=3,s=1,p=1), masked output; 3-term bf16 split
template <int CIN>
__global__ void __launch_bounds__(256) conv_coarse_wmma(
    const float* __restrict__ X, float* __restrict__ Y,
    const __nv_bfloat16* __restrict__ Bhi, const __nv_bfloat16* __restrict__ Blo,
    const float* __restrict__ mask) {
    constexpr int COUT = 96;
    constexpr int LDA = CIN + 8;
    constexpr int KG = CIN / 8;
    constexpr int ITER = 128 * KG / 256;
    extern __shared__ __align__(256) char smem[];
    __nv_bfloat16* sAh = reinterpret_cast<__nv_bfloat16*>(smem);
    __nv_bfloat16* sAl = sAh + 128 * LDA;
    float* sOut = reinterpret_cast<float*>(smem);   // reused after mainloop

    int tid = threadIdx.x, wid = tid >> 5;
    int o0 = blockIdx.x * 128;

    wmma::fragment<wmma::accumulator, 16, 16, 16, float> acc[6];
#pragma unroll
    for (int i = 0; i < 6; i++) wmma::fill_fragment(acc[i], 0.0f);

    for (int tap = 0; tap < 27; tap++) {
        int dz = tap / 9 - 1, dy = (tap / 3) % 3 - 1, dx = tap % 3 - 1;
        __syncthreads();
#pragma unroll
        for (int it = 0; it < ITER; it++) {
            int i = tid + it * 256;
            int r = i / KG, g = i - r * KG;
            int k = g * 8;
            int o = o0 + r;
            int oz = o >> 12, oy = (o >> 6) & 63, ox = o & 63;
            int nz = oz + dz, ny = oy + dy, nx = ox + dx;
            bool ok = (unsigned)nz < (unsigned)GD1 && (unsigned)ny < (unsigned)GH1 &&
                      (unsigned)nx < (unsigned)GW1;
            float4 a = make_float4(0.f, 0.f, 0.f, 0.f), b = a;
            if (ok) {
                const float* s = X + (size_t)((nz * GH1 + ny) * GW1 + nx) * CS + k;
                a = *reinterpret_cast<const float4*>(s);
                b = *reinterpret_cast<const float4*>(s + 4);
            }
            uint32_t h0, h1, h2, h3, l0, l1, l2, l3;
            packpair(a.x, a.y, h0, l0); packpair(a.z, a.w, h1, l1);
            packpair(b.x, b.y, h2, l2); packpair(b.z, b.w, h3, l3);
            *reinterpret_cast<uint4*>(sAh + r * LDA + k) = make_uint4(h0, h1, h2, h3);
            *reinterpret_cast<uint4*>(sAl + r * LDA + k) = make_uint4(l0, l1, l2, l3);
        }
        __syncthreads();
        const __nv_bfloat16* bh = Bhi + (size_t)tap * CIN * COUT;
        const __nv_bfloat16* bl = Blo + (size_t)tap * CIN * COUT;
        const __nv_bfloat16* ah = sAh + wid * 16 * LDA;
        const __nv_bfloat16* al = sAl + wid * 16 * LDA;
#pragma unroll
        for (int kt = 0; kt < CIN / 16; kt++) {
            wmma::fragment<wmma::matrix_a, 16, 16, 16, __nv_bfloat16, wmma::row_major> fah, fal;
            wmma::load_matrix_sync(fah, ah + kt * 16, LDA);
            wmma::load_matrix_sync(fal, al + kt * 16, LDA);
#pragma unroll
            for (int nt = 0; nt < 6; nt++) {
                wmma::fragment<wmma::matrix_b, 16, 16, 16, __nv_bfloat16, wmma::row_major> fbh, fbl;
                wmma::load_matrix_sync(fbh, bh + kt * 16 * COUT + nt * 16, COUT);
                wmma::load_matrix_sync(fbl, bl + kt * 16 * COUT + nt * 16, COUT);
                wmma::mma_sync(acc[nt], fah, fbh, acc[nt]);
                wmma::mma_sync(acc[nt], fah, fbl, acc[nt]);
                wmma::mma_sync(acc[nt], fal, fbh, acc[nt]);
            }
        }
    }
    __syncthreads();
#pragma unroll
    for (int nt = 0; nt < 6; nt++)
        wmma::store_matrix_sync(sOut + wid * 16 * COUT + nt * 16, acc[nt], COUT,
                                wmma::mem_row_major);
    __syncthreads();
    for (int i = tid; i < 128 * 24; i += 256) {
        int r = i / 24, c = i - r * 24;
        float mv = mask[o0 + r];
        float4 v = reinterpret_cast<const float4*>(sOut + r * COUT)[c];
        v.x *= mv; v.y *= mv; v.z *= mv; v.w *= mv;
        *reinterpret_cast<float4*>(&Y[(size_t)(o0 + r) * CS + c * 4]) = v;
    }
}

// ---------------- small helpers (unchanged from R6 winner) ----------------
__global__ void repack_kernel(const float* __restrict__ w, float* __restrict__ o,
                              int k3, int cin, int cout) {
    int i = blockIdx.x * blockDim.x + threadIdx.x;
    int tot = k3 * cin * cout;
    if (i >= tot) return;
    int co = i % cout;
    int r  = i / cout;
    int ci = r % cin;
    int t  = r / cin;
    o[(t * cout + co) * cin + ci] = w[i];
}

__global__ void scatter_kernel(const float* __restrict__ f, const int* __restrict__ coors,
                               float* __restrict__ X, int n) {
    int p = blockIdx.x * blockDim.x + threadIdx.x;
    if (p >= n) return;
    int z = coors[p * 4 + 1], y = coors[p * 4 + 2], x = coors[p * 4 + 3];
    size_t vox = (size_t)((z * GH0 + y) * GW0 + x) * FS;
    X[vox + 0] = f[p * 3 + 0];
    X[vox + 1] = f[p * 3 + 1];
    X[vox + 2] = f[p * 3 + 2];
}

__global__ void mask_kernel(const int* __restrict__ coors, float* __restrict__ mask, int n) {
    int p = blockIdx.x * blockDim.x + threadIdx.x;
    if (p >= n) return;
    int z = coors[p * 4 + 1], y = coors[p * 4 + 2], x = coors[p * 4 + 3];
    int zo[2], yo[2], xo[2];
    int nzc = 0, nyc = 0, nxc = 0;
    if ((z & 1) == 0) { zo[nzc++] = z >> 1; }
    else { zo[nzc++] = z >> 1; if ((z >> 1) + 1 < GD1) zo[nzc++] = (z >> 1) + 1; }
    if ((y & 1) == 0) { yo[nyc++] = y >> 1; }
    else { yo[nyc++] = y >> 1; if ((y >> 1) + 1 < GH1) yo[nyc++] = (y >> 1) + 1; }
    if ((x & 1) == 0) { xo[nxc++] = x >> 1; }
    else { xo[nxc++] = x >> 1; if ((x >> 1) + 1 < GW1) xo[nxc++] = (x >> 1) + 1; }
    for (int a = 0; a < nzc; a++)
        for (int b = 0; b < nyc; b++)
            for (int c = 0; c < nxc; c++)
                mask[(zo[a] * GH1 + yo[b]) * GW1 + xo[c]] = 1.0f;
}

__device__ __forceinline__ void fma4(float4& a, float4 w, float x) {
    a.x = fmaf(w.x, x, a.x);
    a.y = fmaf(w.y, x, a.y);
    a.z = fmaf(w.z, x, a.z);
    a.w = fmaf(w.w, x, a.w);
}

template <int CIN>
__device__ __forceinline__ void dotrow4(const float* __restrict__ w,
                                        const float* __restrict__ xv, float4& a) {
#pragma unroll
    for (int c = 0; c < CIN; c += 4) {
        float4 wv = *reinterpret_cast<const float4*>(w + c);
        float4 x4 = *reinterpret_cast<const float4*>(xv + c);
        a.x = fmaf(wv.x, x4.x, a.x);
        a.y = fmaf(wv.y, x4.y, a.y);
        a.z = fmaf(wv.z, x4.z, a.z);
        a.w = fmaf(wv.w, x4.w, a.w);
    }
}

template <int CIN, int COUT, int XPAD>
__device__ __forceinline__ void compute_tile(const float* __restrict__ xs,
                                             const float* __restrict__ wp,
                                             float4 (&acc)[8], int tm) {
#pragma unroll 8
    for (int ci = 0; ci < CIN; ci++) {
        float4 w4 = *reinterpret_cast<const float4*>(wp + ci * COUT);
        float4 xa = *reinterpret_cast<const float4*>(xs + ci * XPAD + tm * 8);
        float4 xb = *reinterpret_cast<const float4*>(xs + ci * XPAD + tm * 8 + 4);
        fma4(acc[0], w4, xa.x); fma4(acc[1], w4, xa.y);
        fma4(acc[2], w4, xa.z); fma4(acc[3], w4, xa.w);
        fma4(acc[4], w4, xb.x); fma4(acc[5], w4, xb.y);
        fma4(acc[6], w4, xb.z); fma4(acc[7], w4, xb.w);
    }
}

__global__ void __launch_bounds__(32) conv_sub0_kernel(
    const float* __restrict__ X, float* __restrict__ Y,
    const int* __restrict__ coors, const float* __restrict__ W, int n) {
    __shared__ float xs[81];
    int p = blockIdx.x;
    if (p >= n) return;
    int z = coors[p * 4 + 1], y = coors[p * 4 + 2], x = coors[p * 4 + 3];
    int t = threadIdx.x;
    for (int i = t; i < 81; i += 32) {
        int tap = i / 3, ci = i % 3;
        int nz = z + tap / 9 - 1;
        int ny = y + (tap / 3) % 3 - 1;
        int nx = x + tap % 3 - 1;
        bool ok = (unsigned)nz < (unsigned)GD0 && (unsigned)ny < (unsigned)GH0 &&
                  (unsigned)nx < (unsigned)GW0;
        xs[i] = ok ? X[(size_t)((nz * GH0 + ny) * GW0 + nx) * FS + ci] : 0.0f;
    }
    __syncthreads();
    float a = 0.f;
#pragma unroll
    for (int i = 0; i < 81; i++) a = fmaf(W[i * 32 + t], xs[i], a);
    size_t v = (size_t)((z * GH0 + y) * GW0 + x) * FS;
    Y[v + t] = a;
}

template <int CIN, int COUT, int TM>
__global__ void __launch_bounds__((COUT / 4) * TM) conv_fine_tiled(
    const float* __restrict__ X, float* __restrict__ Y,
    const int* __restrict__ coors, const float* __restrict__ Wt, int n) {
    constexpr int TC = COUT / 4;
    constexpr int THREADS = TC * TM;
    constexpr int MT = TM * 8;
    constexpr int XPAD = MT + 4;
    constexpr int C4 = CIN / 4;
    __shared__ __align__(16) float xs[CIN * XPAD];
    __shared__ int s_z[MT], s_y[MT], s_x[MT];
    int t = threadIdx.x;
    int p0 = blockIdx.x * MT;
    for (int i = t; i < MT; i += THREADS) {
        int p = p0 + i;
        int zz = -4, yy = 0, xv = 0;
        if (p < n) { zz = coors[p * 4 + 1]; yy = coors[p * 4 + 2]; xv = coors[p * 4 + 3]; }
        s_z[i] = zz; s_y[i] = yy; s_x[i] = xv;
    }
    float4 acc[8];
#pragma unroll
    for (int j = 0; j < 8; j++) acc[j] = make_float4(0.f, 0.f, 0.f, 0.f);
    int tc = t % TC, tm = t / TC;

    for (int tap = 0; tap < 27; tap++) {
        int dz = tap / 9 - 1, dy = (tap / 3) % 3 - 1, dx = tap % 3 - 1;
        __syncthreads();
        for (int i = t; i < MT * C4; i += THREADS) {
            int m = i / C4, c4 = i - m * C4;
            int nz = s_z[m] + dz, ny = s_y[m] + dy, nx = s_x[m] + dx;
            bool ok = (unsigned)nz < (unsigned)GD0 && (unsigned)ny < (unsigned)GH0 &&
                      (unsigned)nx < (unsigned)GW0;
            float4 v = make_float4(0.f, 0.f, 0.f, 0.f);
            if (ok) v = *reinterpret_cast<const float4*>(
                &X[(size_t)((nz * GH0 + ny) * GW0 + nx) * FS + c4 * 4]);
            xs[(c4 * 4 + 0) * XPAD + m] = v.x;
            xs[(c4 * 4 + 1) * XPAD + m] = v.y;
            xs[(c4 * 4 + 2) * XPAD + m] = v.z;
            xs[(c4 * 4 + 3) * XPAD + m] = v.w;
        }
        __syncthreads();
        compute_tile<CIN, COUT, XPAD>(xs, Wt + (size_t)tap * CIN * COUT + tc * 4, acc, tm);
    }
#pragma unroll
    for (int j = 0; j < 8; j++) {
        int m = tm * 8 + j;
        int p = p0 + m;
        if (p < n) {
            size_t v = (size_t)((s_z[m] * GH0 + s_y[m]) * GW0 + s_x[m]) * FS;
            *reinterpret_cast<float4*>(&Y[v + tc * 4]) = acc[j];
        }
    }
}

template <int CIN, int COUT, int TM, int XSTR, int NTAPS, int MODE>
__global__ void __launch_bounds__((COUT / 4) * TM) conv_grid_tiled(
    const float* __restrict__ X, float* __restrict__ Y,
    const float* __restrict__ Wt, const float* __restrict__ mask) {
    constexpr int TC = COUT / 4;
    constexpr int THREADS = TC * TM;
    constexpr int MT = TM * 8;
    constexpr int XPAD = MT + 4;
    constexpr int C4 = CIN / 4;
    __shared__ __align__(16) float xs[CIN * XPAD];
    __shared__ float s_mk[MT];
    int t = threadIdx.x;
    int o0 = blockIdx.x * MT;
    if (MODE == 0) {
        for (int i = t; i < MT; i += THREADS) s_mk[i] = mask[o0 + i];
    }
    float4 acc[8];
#pragma unroll
    for (int j = 0; j < 8; j++) acc[j] = make_float4(0.f, 0.f, 0.f, 0.f);
    int tc = t % TC, tm = t / TC;

    for (int tap = 0; tap < NTAPS; tap++) {
        int dz, dy, dx;
        if (NTAPS == 27) { dz = tap / 9 - 1; dy = (tap / 3) % 3 - 1; dx = tap % 3 - 1; }
        else             { dz = tap >> 2;    dy = (tap >> 1) & 1;    dx = tap & 1; }
        __syncthreads();
        for (int i = t; i < MT * C4; i += THREADS) {
            int m = i / C4, c4 = i - m * C4;
            int o = o0 + m;
            int oz, oy, ox;
            if (MODE == 2) { oz = o >> 10; oy = (o >> 5) & 31; ox = o & 31; }
            else           { oz = o >> 12; oy = (o >> 6) & 63; ox = o & 63; }
            int nz, ny, nx;
            bool ok;
            size_t base;
            if (MODE == 0) {
                nz = oz + dz; ny = oy + dy; nx = ox + dx;
                ok = (unsigned)nz < (unsigned)GD1 && (unsigned)ny < (unsigned)GH1 &&
                     (unsigned)nx < (unsigned)GW1;
                base = (size_t)((nz * GH1 + ny) * GW1 + nx) * XSTR;
            } else if (MODE == 1) {
                nz = 2 * oz + dz; ny = 2 * oy + dy; nx = 2 * ox + dx;
                ok = (unsigned)nz < (unsigned)GD0 && (unsigned)ny < (unsigned)GH0 &&
                     (unsigned)nx < (unsigned)GW0;
                base = (size_t)((nz * GH0 + ny) * GW0 + nx) * XSTR;
            } else {
                nz = 2 * oz + dz; ny = 2 * oy + dy; nx = 2 * ox + dx;
                ok = true;
                base = (size_t)((nz * GH1 + ny) * GW1 + nx) * XSTR;
            }
            float4 v = make_float4(0.f, 0.f, 0.f, 0.f);
            if (ok) v = *reinterpret_cast<const float4*>(&X[base + c4 * 4]);
            xs[(c4 * 4 + 0) * XPAD + m] = v.x;
            xs[(c4 * 4 + 1) * XPAD + m] = v.y;
            xs[(c4 * 4 + 2) * XPAD + m] = v.z;
            xs[(c4 * 4 + 3) * XPAD + m] = v.w;
        }
        __syncthreads();
        compute_tile<CIN, COUT, XPAD>(xs, Wt + (size_t)tap * CIN * COUT + tc * 4, acc, tm);
    }
#pragma unroll
    for (int j = 0; j < 8; j++) {
        int m = tm * 8 + j;
        int o = o0 + m;
        float4 r = acc[j];
        if (MODE == 0) {
            float mv = s_mk[m];
            r.x *= mv; r.y *= mv; r.z *= mv; r.w *= mv;
        }
        *reinterpret_cast<float4*>(&Y[(size_t)o * CS + tc * 4]) = r;
    }
}

__global__ void __launch_bounds__(64) inv1_kernel(
    const float* __restrict__ X2, float* __restrict__ Y,
    const float* __restrict__ Wt, const float* __restrict__ mask) {
    constexpr int CIN = 96;
    __shared__ __align__(16) float xs[CIN];
    int o = blockIdx.x;
    int t = threadIdx.x;
    float mv = mask[o];
    if (mv == 0.0f) { Y[o * CS + t] = 0.0f; return; }
    int oz = o >> 12, oy = (o >> 6) & 63, ox = o & 63;
    int m = (((oz >> 1) * GH2) + (oy >> 1)) * GW2 + (ox >> 1);
    int tap = ((oz & 1) * 2 + (oy & 1)) * 2 + (ox & 1);
    for (int c = t; c < CIN; c += 64) xs[c] = X2[(size_t)m * CS + c];
    __syncthreads();
    float4 acc = make_float4(0.f, 0.f, 0.f, 0.f);
    dotrow4<CIN>(Wt + (tap * 64 + t) * CIN, xs, acc);
    Y[o * CS + t] = (acc.x + acc.y + acc.z + acc.w) * mv;
}

__global__ void __launch_bounds__(32) inv0_kernel(
    const float* __restrict__ X, float* __restrict__ out,
    const int* __restrict__ coors, const float* __restrict__ Wt, int n) {
    constexpr int CIN = 64, COUT = 32;
    __shared__ __align__(16) float xs[CIN];
    int p = blockIdx.x;
    if (p >= n) return;
    int z = coors[p * 4 + 1], y = coors[p * 4 + 2], x = coors[p * 4 + 3];
    int t = threadIdx.x;

    int mzv[2], wzv[2], myv[2], wyv[2], mxv[2], wxv[2];
    int nzc = 0, nyc = 0, nxc = 0;
    if ((z & 1) == 0) { mzv[0] = z >> 1; wzv[0] = 1; nzc = 1; }
    else {
        mzv[nzc] = z >> 1; wzv[nzc] = 2; nzc++;
        if ((z >> 1) + 1 < GD1) { mzv[nzc] = (z >> 1) + 1; wzv[nzc] = 0; nzc++; }
    }
    if ((y & 1) == 0) { myv[0] = y >> 1; wyv[0] = 1; nyc = 1; }
    else {
        myv[nyc] = y >> 1; wyv[nyc] = 2; nyc++;
        if ((y >> 1) + 1 < GH1) { myv[nyc] = (y >> 1) + 1; wyv[nyc] = 0; nyc++; }
    }
    if ((x & 1) == 0) { mxv[0] = x >> 1; wxv[0] = 1; nxc = 1; }
    else {
        mxv[nxc] = x >> 1; wxv[nxc] = 2; nxc++;
        if ((x >> 1) + 1 < GW1) { mxv[nxc] = (x >> 1) + 1; wxv[nxc] = 0; nxc++; }
    }

    float4 acc = make_float4(0.f, 0.f, 0.f, 0.f);
    for (int a = 0; a < nzc; a++)
        for (int b = 0; b < nyc; b++)
            for (int c = 0; c < nxc; c++) {
                int m = ((mzv[a] * GH1) + myv[b]) * GW1 + mxv[c];
                int tap = (wzv[a] * 3 + wyv[b]) * 3 + wxv[c];
                xs[t] = X[(size_t)m * CS + t];
                xs[t + 32] = X[(size_t)m * CS + t + 32];
                __syncthreads();
                dotrow4<CIN>(Wt + (tap * COUT + t) * CIN, xs, acc);
                __syncthreads();
            }
    out[(size_t)p * COUT + t] = acc.x + acc.y + acc.z + acc.w;
}

// ---------------- launch ----------------
extern "C" void kernel_launch(void* const* d_in, const int* in_sizes, int n_in,
                              void* d_out, int out_size) {
    const float* features = (const float*)d_in[0];
    const int* coors      = (const int*)d_in[1];
    int wb = n_in - 10;
    const float* w_sub0  = (const float*)d_in[wb + 0];
    const float* w_sub1  = (const float*)d_in[wb + 1];
    const float* w_sub2  = (const float*)d_in[wb + 2];
    const float* w_sub3  = (const float*)d_in[wb + 3];
    const float* w_down0 = (const float*)d_in[wb + 4];
    const float* w_sub4  = (const float*)d_in[wb + 5];
    const float* w_sub5  = (const float*)d_in[wb + 6];
    const float* w_down1 = (const float*)d_in[wb + 7];
    const float* w_inv1  = (const float*)d_in[wb + 8];
    const float* w_inv0  = (const float*)d_in[wb + 9];

    int n = in_sizes[0] / 3;

    float *fA, *fB, *cA, *cB, *c2p, *maskp, *pwi1, *pwi0;
    __nv_bfloat16 *b4h, *b4l, *b5h, *b5l;
    cudaGetSymbolAddress((void**)&fA, g_fineA);
    cudaGetSymbolAddress((void**)&fB, g_fineB);
    cudaGetSymbolAddress((void**)&cA, g_cA);
    cudaGetSymbolAddress((void**)&cB, g_cB);
    cudaGetSymbolAddress((void**)&c2p, g_c2);
    cudaGetSymbolAddress((void**)&maskp, g_mask);
    cudaGetSymbolAddress((void**)&pwi1, g_wi1);
    cudaGetSymbolAddress((void**)&pwi0, g_wi0);
    cudaGetSymbolAddress((void**)&b4h, g_b4hi);
    cudaGetSymbolAddress((void**)&b4l, g_b4lo);
    cudaGetSymbolAddress((void**)&b5h, g_b5hi);
    cudaGetSymbolAddress((void**)&b5l, g_b5lo);

    // dynamic smem for wmma kernels: max(A hi+lo, out tile)
    constexpr int SMEM4 = 128 * 96 * 4;                    // 49152 (out tile dominates)
    constexpr int SMEM5 = 2 * 128 * (96 + 8) * 2;          // 53248
    cudaFuncSetAttribute(conv_coarse_wmma<64>, cudaFuncAttributeMaxDynamicSharedMemorySize, SMEM4);
    cudaFuncSetAttribute(conv_coarse_wmma<96>, cudaFuncAttributeMaxDynamicSharedMemorySize, SMEM5);

    // launches 1..5: setup + small fine layers
    scatter_kernel<<<(n + 255) / 256, 256>>>(features, coors, fA, n);            // 1
    mask_kernel<<<(n + 255) / 256, 256>>>(coors, maskp, n);                      // 2
    conv_sub0_kernel<<<n, 32>>>(fA, fB, coors, w_sub0, n);                       // 3
    conv_fine_tiled<32, 32, 32><<<(n + 255) / 256, 256>>>(fB, fA, coors, w_sub1, n);  // 4
    conv_fine_tiled<32, 64, 16><<<(n + 127) / 128, 256>>>(fA, fB, coors, w_sub2, n);  // 5
    // launch 6: PROFILED by ncu (-s 5 -c 1) -> heaviest fine layer
    conv_fine_tiled<64, 64, 16><<<(n + 127) / 128, 256>>>(fB, fA, coors, w_sub3, n);  // 6

    conv_grid_tiled<64, 64, 16, FS, 27, 1><<<NC1 / 128, 256>>>(fA, cA, w_down0, nullptr); // 7

    // weight preprocessing
    bprep_kernel<<<(27 * 64 * 96 + 255) / 256, 256>>>(w_sub4, b4h, b4l, 27 * 64 * 96);  // 8
    bprep_kernel<<<(27 * 96 * 96 + 255) / 256, 256>>>(w_sub5, b5h, b5l, 27 * 96 * 96);  // 9
    repack_kernel<<<(8 * 96 * 64 + 255) / 256, 256>>>(w_inv1, pwi1, 8, 96, 64);  // 10
    repack_kernel<<<(27 * 64 * 32 + 255) / 256, 256>>>(w_inv0, pwi0, 27, 64, 32);// 11

    // coarse level: wmma bf16 3-term split
    conv_coarse_wmma<64><<<NC1 / 128, 256, SMEM4>>>(cA, cB, b4h, b4l, maskp);    // 12
    conv_coarse_wmma<96><<<NC1 / 128, 256, SMEM5>>>(cB, cA, b5h, b5l, maskp);    // 13

    conv_grid_tiled<96, 96, 8, CS, 8, 2><<<NC2 / 64, 192>>>(cA, c2p, w_down1, nullptr); // 14

    inv1_kernel<<<NC1, 64>>>(c2p, cB, pwi1, maskp);                              // 15
    inv0_kernel<<<n, 32>>>(cB, (float*)d_out, coors, pwi0, n);                   // 16
}

// round 10
// speedup vs baseline: 1.0451x; 1.0451x over previous
#include <cuda_runtime.h>
#include <cuda_bf16.h>
#include <mma.h>
#include <cstdint>

using namespace nvcuda;

// ---------------- geometry ----------------
#define GD0 27
#define GH0 127
#define GW0 127
#define NVOX (GD0*GH0*GW0)        // 435483
#define GD1 14
#define GH1 64
#define GW1 64
#define NC1 (GD1*GH1*GW1)         // 57344
#define GD2 7
#define GH2 32
#define GW2 32
#define NC2 (GD2*GH2*GW2)         // 7168
#define FS 64
#define CS 96

// ---------------- static scratch (zero-init; inactive voxels never written) ----
__device__ float g_fineA[(size_t)NVOX * FS];
__device__ float g_fineB[(size_t)NVOX * FS];
__device__ float g_cA[NC1 * CS];          // sub5 output (f32, for down1 / inv1 / inv0)
__device__ float g_c2[NC2 * CS];
__device__ float g_mask[NC1];
__device__ float g_wi1[8 * 64 * 96];
__device__ float g_wi0[27 * 32 * 64];
// bf16 hi/lo coarse activation buffers
__device__ __align__(256) __nv_bfloat16 g_cAh[NC1 * CS];
__device__ __align__(256) __nv_bfloat16 g_cAl[NC1 * CS];
__device__ __align__(256) __nv_bfloat16 g_cBh[NC1 * CS];
__device__ __align__(256) __nv_bfloat16 g_cBl[NC1 * CS];
// bf16 hi/lo weight images, ORIGINAL [tap][ci][co] layout
__device__ __align__(256) __nv_bfloat16 g_b4hi[27 * 64 * 96];
__device__ __align__(256) __nv_bfloat16 g_b4lo[27 * 64 * 96];
__device__ __align__(256) __nv_bfloat16 g_b5hi[27 * 96 * 96];
__device__ __align__(256) __nv_bfloat16 g_b5lo[27 * 96 * 96];

// ---------------- helpers ----------------
__device__ __forceinline__ void packpair(float x, float y, uint32_t& h, uint32_t& l) {
    __nv_bfloat16 hx = __float2bfloat16(x), hy = __float2bfloat16(y);
    __nv_bfloat16 lx = __float2bfloat16(x - __bfloat162float(hx));
    __nv_bfloat16 ly = __float2bfloat16(y - __bfloat162float(hy));
    __nv_bfloat162 hh; hh.x = hx; hh.y = hy;
    __nv_bfloat162 ll; ll.x = lx; ll.y = ly;
    h = *reinterpret_cast<uint32_t*>(&hh);
    l = *reinterpret_cast<uint32_t*>(&ll);
}

__global__ void bprep_kernel(const float* __restrict__ W, __nv_bfloat16* __restrict__ hi,
                             __nv_bfloat16* __restrict__ lo, int tot) {
    int i = blockIdx.x * blockDim.x + threadIdx.x;
    if (i >= tot) return;
    float v = W[i];
    __nv_bfloat16 h = __float2bfloat16(v);
    hi[i] = h;
    lo[i] = __float2bfloat16(v - __bfloat162float(h));
}

// ---------------- wmma coarse conv (k=3,s=1,p=1): bf16 hi/lo in, 3-term split
template <int CIN, bool OUT16>
__global__ void __launch_bounds__(256) conv_coarse_wmma(
    const __nv_bfloat16* __restrict__ Xh, const __nv_bfloat16* __restrict__ Xl,
    float* __restrict__ Yf, __nv_bfloat16* __restrict__ Yh, __nv_bfloat16* __restrict__ Yl,
    const __nv_bfloat16* __restrict__ Bhi, const __nv_bfloat16* __restrict__ Blo,
    const float* __restrict__ mask) {
    constexpr int COUT = 96;
    constexpr int LDA = CIN + 8;
    constexpr int KG = CIN / 8;
    constexpr int ITER = 128 * KG / 256;
    constexpr int BG = CIN * COUT / 8;
    extern __shared__ __align__(256) char smem[];
    __nv_bfloat16* sAh = reinterpret_cast<__nv_bfloat16*>(smem);
    __nv_bfloat16* sAl = sAh + 128 * LDA;
    __nv_bfloat16* sBh = sAl + 128 * LDA;
    __nv_bfloat16* sBl = sBh + CIN * COUT;
    float* sOut = reinterpret_cast<float*>(smem);

    int tid = threadIdx.x, wid = tid >> 5;
    int o0 = blockIdx.x * 128;

    wmma::fragment<wmma::accumulator, 16, 16, 16, float> acc[6];
#pragma unroll
    for (int i = 0; i < 6; i++) wmma::fill_fragment(acc[i], 0.0f);

    for (int tap = 0; tap < 27; tap++) {
        int dz = tap / 9 - 1, dy = (tap / 3) % 3 - 1, dx = tap % 3 - 1;
        __syncthreads();
        {
            const uint4* bh = reinterpret_cast<const uint4*>(Bhi + (size_t)tap * CIN * COUT);
            const uint4* bl = reinterpret_cast<const uint4*>(Blo + (size_t)tap * CIN * COUT);
            for (int j = tid; j < BG; j += 256) {
                reinterpret_cast<uint4*>(sBh)[j] = bh[j];
                reinterpret_cast<uint4*>(sBl)[j] = bl[j];
            }
        }
#pragma unroll
        for (int it = 0; it < ITER; it++) {
            int i = tid + it * 256;
            int r = i / KG, g = i - r * KG;
            int k = g * 8;
            int o = o0 + r;
            int oz = o >> 12, oy = (o >> 6) & 63, ox = o & 63;
            int nz = oz + dz, ny = oy + dy, nx = ox + dx;
            bool ok = (unsigned)nz < (unsigned)GD1 && (unsigned)ny < (unsigned)GH1 &&
                      (unsigned)nx < (unsigned)GW1;
            uint4 vh = make_uint4(0u, 0u, 0u, 0u), vl = vh;
            if (ok) {
                size_t base = (size_t)((nz * GH1 + ny) * GW1 + nx) * CS + k;
                vh = *reinterpret_cast<const uint4*>(Xh + base);
                vl = *reinterpret_cast<const uint4*>(Xl + base);
            }
            *reinterpret_cast<uint4*>(sAh + r * LDA + k) = vh;
            *reinterpret_cast<uint4*>(sAl + r * LDA + k) = vl;
        }
        __syncthreads();
        const __nv_bfloat16* ah = sAh + wid * 16 * LDA;
        const __nv_bfloat16* al = sAl + wid * 16 * LDA;
#pragma unroll
        for (int kt = 0; kt < CIN / 16; kt++) {
            wmma::fragment<wmma::matrix_a, 16, 16, 16, __nv_bfloat16, wmma::row_major> fah, fal;
            wmma::load_matrix_sync(fah, ah + kt * 16, LDA);
            wmma::load_matrix_sync(fal, al + kt * 16, LDA);
#pragma unroll
            for (int nt = 0; nt < 6; nt++) {
                wmma::fragment<wmma::matrix_b, 16, 16, 16, __nv_bfloat16, wmma::row_major> fbh, fbl;
                wmma::load_matrix_sync(fbh, sBh + kt * 16 * COUT + nt * 16, COUT);
                wmma::load_matrix_sync(fbl, sBl + kt * 16 * COUT + nt * 16, COUT);
                wmma::mma_sync(acc[nt], fah, fbh, acc[nt]);
                wmma::mma_sync(acc[nt], fah, fbl, acc[nt]);
                wmma::mma_sync(acc[nt], fal, fbh, acc[nt]);
            }
        }
    }
    __syncthreads();
#pragma unroll
    for (int nt = 0; nt < 6; nt++)
        wmma::store_matrix_sync(sOut + wid * 16 * COUT + nt * 16, acc[nt], COUT,
                                wmma::mem_row_major);
    __syncthreads();
    if (OUT16) {
        for (int i = tid; i < 128 * 12; i += 256) {
            int r = i / 12, g = i - r * 12;
            int k = g * 8;
            float mv = mask[o0 + r];
            const float* s = sOut + r * COUT + k;
            float4 a = *reinterpret_cast<const float4*>(s);
            float4 b = *reinterpret_cast<const float4*>(s + 4);
            a.x *= mv; a.y *= mv; a.z *= mv; a.w *= mv;
            b.x *= mv; b.y *= mv; b.z *= mv; b.w *= mv;
            uint32_t h0, h1, h2, h3, l0, l1, l2, l3;
            packpair(a.x, a.y, h0, l0); packpair(a.z, a.w, h1, l1);
            packpair(b.x, b.y, h2, l2); packpair(b.z, b.w, h3, l3);
            size_t base = (size_t)(o0 + r) * CS + k;
            *reinterpret_cast<uint4*>(Yh + base) = make_uint4(h0, h1, h2, h3);
            *reinterpret_cast<uint4*>(Yl + base) = make_uint4(l0, l1, l2, l3);
        }
    } else {
        for (int i = tid; i < 128 * 24; i += 256) {
            int r = i / 24, c = i - r * 24;
            float mv = mask[o0 + r];
            float4 v = reinterpret_cast<const float4*>(sOut + r * COUT)[c];
            v.x *= mv; v.y *= mv; v.z *= mv; v.w *= mv;
            *reinterpret_cast<float4*>(&Yf[(size_t)(o0 + r) * CS + c * 4]) = v;
        }
    }
}

// ---------------- small helpers ----------------
__global__ void repack_kernel(const float* __restrict__ w, float* __restrict__ o,
                              int k3, int cin, int cout) {
    int i = blockIdx.x * blockDim.x + threadIdx.x;
    int tot = k3 * cin * cout;
    if (i >= tot) return;
    int co = i % cout;
    int r  = i / cout;
    int ci = r % cin;
    int t  = r / cin;
    o[(t * cout + co) * cin + ci] = w[i];
}

__global__ void scatter_kernel(const float* __restrict__ f, const int* __restrict__ coors,
                               float* __restrict__ X, int n) {
    int p = blockIdx.x * blockDim.x + threadIdx.x;
    if (p >= n) return;
    int z = coors[p * 4 + 1], y = coors[p * 4 + 2], x = coors[p * 4 + 3];
    size_t vox = (size_t)((z * GH0 + y) * GW0 + x) * FS;
    X[vox + 0] = f[p * 3 + 0];
    X[vox + 1] = f[p * 3 + 1];
    X[vox + 2] = f[p * 3 + 2];
}

__global__ void mask_kernel(const int* __restrict__ coors, float* __restrict__ mask, int n) {
    int p = blockIdx.x * blockDim.x + threadIdx.x;
    if (p >= n) return;
    int z = coors[p * 4 + 1], y = coors[p * 4 + 2], x = coors[p * 4 + 3];
    int zo[2], yo[2], xo[2];
    int nzc = 0, nyc = 0, nxc = 0;
    if ((z & 1) == 0) { zo[nzc++] = z >> 1; }
    else { zo[nzc++] = z >> 1; if ((z >> 1) + 1 < GD1) zo[nzc++] = (z >> 1) + 1; }
    if ((y & 1) == 0) { yo[nyc++] = y >> 1; }
    else { yo[nyc++] = y >> 1; if ((y >> 1) + 1 < GH1) yo[nyc++] = (y >> 1) + 1; }
    if ((x & 1) == 0) { xo[nxc++] = x >> 1; }
    else { xo[nxc++] = x >> 1; if ((x >> 1) + 1 < GW1) xo[nxc++] = (x >> 1) + 1; }
    for (int a = 0; a < nzc; a++)
        for (int b = 0; b < nyc; b++)
            for (int c = 0; c < nxc; c++)
                mask[(zo[a] * GH1 + yo[b]) * GW1 + xo[c]] = 1.0f;
}

__device__ __forceinline__ void fma4(float4& a, float4 w, float x) {
    a.x = fmaf(w.x, x, a.x);
    a.y = fmaf(w.y, x, a.y);
    a.z = fmaf(w.z, x, a.z);
    a.w = fmaf(w.w, x, a.w);
}

template <int CIN>
__device__ __forceinline__ void dotrow4(const float* __restrict__ w,
                                        const float* __restrict__ xv, float4& a) {
#pragma unroll
    for (int c = 0; c < CIN; c += 4) {
        float4 wv = *reinterpret_cast<const float4*>(w + c);
        float4 x4 = *reinterpret_cast<const float4*>(xv + c);
        a.x = fmaf(wv.x, x4.x, a.x);
        a.y = fmaf(wv.y, x4.y, a.y);
        a.z = fmaf(wv.z, x4.z, a.z);
        a.w = fmaf(wv.w, x4.w, a.w);
    }
}

template <int CIN, int COUT, int XPAD>
__device__ __forceinline__ void compute_tile(const float* __restrict__ xs,
                                             const float* __restrict__ wp,
                                             float4 (&acc)[8], int tm) {
#pragma unroll 8
    for (int ci = 0; ci < CIN; ci++) {
        float4 w4 = *reinterpret_cast<const float4*>(wp + ci * COUT);
        float4 xa = *reinterpret_cast<const float4*>(xs + ci * XPAD + tm * 8);
        float4 xb = *reinterpret_cast<const float4*>(xs + ci * XPAD + tm * 8 + 4);
        fma4(acc[0], w4, xa.x); fma4(acc[1], w4, xa.y);
        fma4(acc[2], w4, xa.z); fma4(acc[3], w4, xa.w);
        fma4(acc[4], w4, xb.x); fma4(acc[5], w4, xb.y);
        fma4(acc[6], w4, xb.z); fma4(acc[7], w4, xb.w);
    }
}

__global__ void __launch_bounds__(32) conv_sub0_kernel(
    const float* __restrict__ X, float* __restrict__ Y,
    const int* __restrict__ coors, const float* __restrict__ W, int n) {
    __shared__ float xs[81];
    int p = blockIdx.x;
    if (p >= n) return;
    int z = coors[p * 4 + 1], y = coors[p * 4 + 2], x = coors[p * 4 + 3];
    int t = threadIdx.x;
    for (int i = t; i < 81; i += 32) {
        int tap = i / 3, ci = i % 3;
        int nz = z + tap / 9 - 1;
        int ny = y + (tap / 3) % 3 - 1;
        int nx = x + tap % 3 - 1;
        bool ok = (unsigned)nz < (unsigned)GD0 && (unsigned)ny < (unsigned)GH0 &&
                  (unsigned)nx < (unsigned)GW0;
        xs[i] = ok ? X[(size_t)((nz * GH0 + ny) * GW0 + nx) * FS + ci] : 0.0f;
    }
    __syncthreads();
    float a = 0.f;
#pragma unroll
    for (int i = 0; i < 81; i++) a = fmaf(W[i * 32 + t], xs[i], a);
    size_t v = (size_t)((z * GH0 + y) * GW0 + x) * FS;
    Y[v + t] = a;
}

template <int CIN, int COUT, int TM>
__global__ void __launch_bounds__((COUT / 4) * TM) conv_fine_tiled(
    const float* __restrict__ X, float* __restrict__ Y,
    const int* __restrict__ coors, const float* __restrict__ Wt, int n) {
    constexpr int TC = COUT / 4;
    constexpr int THREADS = TC * TM;
    constexpr int MT = TM * 8;
    constexpr int XPAD = MT + 4;
    constexpr int C4 = CIN / 4;
    __shared__ __align__(16) float xs[CIN * XPAD];
    __shared__ int s_z[MT], s_y[MT], s_x[MT];
    int t = threadIdx.x;
    int p0 = blockIdx.x * MT;
    for (int i = t; i < MT; i += THREADS) {
        int p = p0 + i;
        int zz = -4, yy = 0, xv = 0;
        if (p < n) { zz = coors[p * 4 + 1]; yy = coors[p * 4 + 2]; xv = coors[p * 4 + 3]; }
        s_z[i] = zz; s_y[i] = yy; s_x[i] = xv;
    }
    float4 acc[8];
#pragma unroll
    for (int j = 0; j < 8; j++) acc[j] = make_float4(0.f, 0.f, 0.f, 0.f);
    int tc = t % TC, tm = t / TC;

    for (int tap = 0; tap < 27; tap++) {
        int dz = tap / 9 - 1, dy = (tap / 3) % 3 - 1, dx = tap % 3 - 1;
        __syncthreads();
        for (int i = t; i < MT * C4; i += THREADS) {
            int m = i / C4, c4 = i - m * C4;
            int nz = s_z[m] + dz, ny = s_y[m] + dy, nx = s_x[m] + dx;
            bool ok = (unsigned)nz < (unsigned)GD0 && (unsigned)ny < (unsigned)GH0 &&
                      (unsigned)nx < (unsigned)GW0;
            float4 v = make_float4(0.f, 0.f, 0.f, 0.f);
            if (ok) v = *reinterpret_cast<const float4*>(
                &X[(size_t)((nz * GH0 + ny) * GW0 + nx) * FS + c4 * 4]);
            xs[(c4 * 4 + 0) * XPAD + m] = v.x;
            xs[(c4 * 4 + 1) * XPAD + m] = v.y;
            xs[(c4 * 4 + 2) * XPAD + m] = v.z;
            xs[(c4 * 4 + 3) * XPAD + m] = v.w;
        }
        __syncthreads();
        compute_tile<CIN, COUT, XPAD>(xs, Wt + (size_t)tap * CIN * COUT + tc * 4, acc, tm);
    }
#pragma unroll
    for (int j = 0; j < 8; j++) {
        int m = tm * 8 + j;
        int p = p0 + m;
        if (p < n) {
            size_t v = (size_t)((s_z[m] * GH0 + s_y[m]) * GW0 + s_x[m]) * FS;
            *reinterpret_cast<float4*>(&Y[v + tc * 4]) = acc[j];
        }
    }
}

// grid conv. MODE 1 = down0 (fine f32 -> coarse bf16 hi/lo). MODE 2 = down1 (f32 -> f32).
template <int CIN, int COUT, int TM, int XSTR, int NTAPS, int MODE>
__global__ void __launch_bounds__((COUT / 4) * TM) conv_grid_tiled(
    const float* __restrict__ X, float* __restrict__ Y,
    __nv_bfloat16* __restrict__ Yh, __nv_bfloat16* __restrict__ Yl,
    const float* __restrict__ Wt) {
    constexpr int TC = COUT / 4;
    constexpr int THREADS = TC * TM;
    constexpr int MT = TM * 8;
    constexpr int XPAD = MT + 4;
    constexpr int C4 = CIN / 4;
    __shared__ __align__(16) float xs[CIN * XPAD];
    int t = threadIdx.x;
    int o0 = blockIdx.x * MT;
    float4 acc[8];
#pragma unroll
    for (int j = 0; j < 8; j++) acc[j] = make_float4(0.f, 0.f, 0.f, 0.f);
    int tc = t % TC, tm = t / TC;

    for (int tap = 0; tap < NTAPS; tap++) {
        int dz, dy, dx;
        if (NTAPS == 27) { dz = tap / 9 - 1; dy = (tap / 3) % 3 - 1; dx = tap % 3 - 1; }
        else             { dz = tap >> 2;    dy = (tap >> 1) & 1;    dx = tap & 1; }
        __syncthreads();
        for (int i = t; i < MT * C4; i += THREADS) {
            int m = i / C4, c4 = i - m * C4;
            int o = o0 + m;
            int oz, oy, ox;
            if (MODE == 2) { oz = o >> 10; oy = (o >> 5) & 31; ox = o & 31; }
            else           { oz = o >> 12; oy = (o >> 6) & 63; ox = o & 63; }
            int nz = 2 * oz + dz, ny = 2 * oy + dy, nx = 2 * ox + dx;
            bool ok;
            size_t base;
            if (MODE == 1) {
                ok = (unsigned)nz < (unsigned)GD0 && (unsigned)ny < (unsigned)GH0 &&
                     (unsigned)nx < (unsigned)GW0;
                base = (size_t)((nz * GH0 + ny) * GW0 + nx) * XSTR;
            } else {
                ok = true;
                base = (size_t)((nz * GH1 + ny) * GW1 + nx) * XSTR;
            }
            float4 v = make_float4(0.f, 0.f, 0.f, 0.f);
            if (ok) v = *reinterpret_cast<const float4*>(&X[base + c4 * 4]);
            xs[(c4 * 4 + 0) * XPAD + m] = v.x;
            xs[(c4 * 4 + 1) * XPAD + m] = v.y;
            xs[(c4 * 4 + 2) * XPAD + m] = v.z;
            xs[(c4 * 4 + 3) * XPAD + m] = v.w;
        }
        __syncthreads();
        compute_tile<CIN, COUT, XPAD>(xs, Wt + (size_t)tap * CIN * COUT + tc * 4, acc, tm);
    }
#pragma unroll
    for (int j = 0; j < 8; j++) {
        int m = tm * 8 + j;
        int o = o0 + m;
        if (MODE == 1) {
            uint32_t h0, h1, l0, l1;
            packpair(acc[j].x, acc[j].y, h0, l0);
            packpair(acc[j].z, acc[j].w, h1, l1);
            size_t base = (size_t)o * CS + tc * 4;
            *reinterpret_cast<uint2*>(Yh + base) = make_uint2(h0, h1);
            *reinterpret_cast<uint2*>(Yl + base) = make_uint2(l0, l1);
        } else {
            *reinterpret_cast<float4*>(&Y[(size_t)o * CS + tc * 4]) = acc[j];
        }
    }
}

__global__ void __launch_bounds__(64) inv1_kernel(
    const float* __restrict__ X2, float* __restrict__ Y,
    const float* __restrict__ Wt, const float* __restrict__ mask) {
    constexpr int CIN = 96;
    __shared__ __align__(16) float xs[CIN];
    int o = blockIdx.x;
    int t = threadIdx.x;
    float mv = mask[o];
    if (mv == 0.0f) { Y[o * CS + t] = 0.0f; return; }
    int oz = o >> 12, oy = (o >> 6) & 63, ox = o & 63;
    int m = (((oz >> 1) * GH2) + (oy >> 1)) * GW2 + (ox >> 1);
    int tap = ((oz & 1) * 2 + (oy & 1)) * 2 + (ox & 1);
    for (int c = t; c < CIN; c += 64) xs[c] = X2[(size_t)m * CS + c];
    __syncthreads();
    float4 acc = make_float4(0.f, 0.f, 0.f, 0.f);
    dotrow4<CIN>(Wt + (tap * 64 + t) * CIN, xs, acc);
    Y[o * CS + t] = (acc.x + acc.y + acc.z + acc.w) * mv;
}

__global__ void __launch_bounds__(32) inv0_kernel(
    const float* __restrict__ X, float* __restrict__ out,
    const int* __restrict__ coors, const float* __restrict__ Wt, int n) {
    constexpr int CIN = 64, COUT = 32;
    __shared__ __align__(16) float xs[CIN];
    int p = blockIdx.x;
    if (p >= n) return;
    int z = coors[p * 4 + 1], y = coors[p * 4 + 2], x = coors[p * 4 + 3];
    int t = threadIdx.x;

    int mzv[2], wzv[2], myv[2], wyv[2], mxv[2], wxv[2];
    int nzc = 0, nyc = 0, nxc = 0;
    if ((z & 1) == 0) { mzv[0] = z >> 1; wzv[0] = 1; nzc = 1; }
    else {
        mzv[nzc] = z >> 1; wzv[nzc] = 2; nzc++;
        if ((z >> 1) + 1 < GD1) { mzv[nzc] = (z >> 1) + 1; wzv[nzc] = 0; nzc++; }
    }
    if ((y & 1) == 0) { myv[0] = y >> 1; wyv[0] = 1; nyc = 1; }
    else {
        myv[nyc] = y >> 1; wyv[nyc] = 2; nyc++;
        if ((y >> 1) + 1 < GH1) { myv[nyc] = (y >> 1) + 1; wyv[nyc] = 0; nyc++; }
    }
    if ((x & 1) == 0) { mxv[0] = x >> 1; wxv[0] = 1; nxc = 1; }
    else {
        mxv[nxc] = x >> 1; wxv[nxc] = 2; nxc++;
        if ((x >> 1) + 1 < GW1) { mxv[nxc] = (x >> 1) + 1; wxv[nxc] = 0; nxc++; }
    }

    float4 acc = make_float4(0.f, 0.f, 0.f, 0.f);
    for (int a = 0; a < nzc; a++)
        for (int b = 0; b < nyc; b++)
            for (int c = 0; c < nxc; c++) {
                int m = ((mzv[a] * GH1) + myv[b]) * GW1 + mxv[c];
                int tap = (wzv[a] * 3 + wyv[b]) * 3 + wxv[c];
                xs[t] = X[(size_t)m * CS + t];
                xs[t + 32] = X[(size_t)m * CS + t + 32];
                __syncthreads();
                dotrow4<CIN>(Wt + (tap * COUT + t) * CIN, xs, acc);
                __syncthreads();
            }
    out[(size_t)p * COUT + t] = acc.x + acc.y + acc.z + acc.w;
}

// ---------------- launch ----------------
extern "C" void kernel_launch(void* const* d_in, const int* in_sizes, int n_in,
                              void* d_out, int out_size) {
    const float* features = (const float*)d_in[0];
    const int* coors      = (const int*)d_in[1];
    int wb = n_in - 10;
    const float* w_sub0  = (const float*)d_in[wb + 0];
    const float* w_sub1  = (const float*)d_in[wb + 1];
    const float* w_sub2  = (const float*)d_in[wb + 2];
    const float* w_sub3  = (const float*)d_in[wb + 3];
    const float* w_down0 = (const float*)d_in[wb + 4];
    const float* w_sub4  = (const float*)d_in[wb + 5];
    const float* w_sub5  = (const float*)d_in[wb + 6];
    const float* w_down1 = (const float*)d_in[wb + 7];
    const float* w_inv1  = (const float*)d_in[wb + 8];
    const float* w_inv0  = (const float*)d_in[wb + 9];

    int n = in_sizes[0] / 3;

    float *fA, *fB, *cA, *c2p, *maskp, *pwi1, *pwi0;
    __nv_bfloat16 *cAh, *cAl, *cBh, *cBl, *b4h, *b4l, *b5h, *b5l;
    cudaGetSymbolAddress((void**)&fA, g_fineA);
    cudaGetSymbolAddress((void**)&fB, g_fineB);
    cudaGetSymbolAddress((void**)&cA, g_cA);
    cudaGetSymbolAddress((void**)&c2p, g_c2);
    cudaGetSymbolAddress((void**)&maskp, g_mask);
    cudaGetSymbolAddress((void**)&pwi1, g_wi1);
    cudaGetSymbolAddress((void**)&pwi0, g_wi0);
    cudaGetSymbolAddress((void**)&cAh, g_cAh);
    cudaGetSymbolAddress((void**)&cAl, g_cAl);
    cudaGetSymbolAddress((void**)&cBh, g_cBh);
    cudaGetSymbolAddress((void**)&cBl, g_cBl);
    cudaGetSymbolAddress((void**)&b4h, g_b4hi);
    cudaGetSymbolAddress((void**)&b4l, g_b4lo);
    cudaGetSymbolAddress((void**)&b5h, g_b5hi);
    cudaGetSymbolAddress((void**)&b5l, g_b5lo);

    constexpr int SMEM4 = 2 * 128 * (64 + 8) * 2 + 2 * 64 * 96 * 2;   // 61440
    constexpr int SMEM5 = 2 * 128 * (96 + 8) * 2 + 2 * 96 * 96 * 2;   // 90112
    cudaFuncSetAttribute(conv_coarse_wmma<64, true>,
                         cudaFuncAttributeMaxDynamicSharedMemorySize, SMEM4);
    cudaFuncSetAttribute(conv_coarse_wmma<96, false>,
                         cudaFuncAttributeMaxDynamicSharedMemorySize, SMEM5);

    scatter_kernel<<<(n + 255) / 256, 256>>>(features, coors, fA, n);            // 1
    conv_sub0_kernel<<<n, 32>>>(fA, fB, coors, w_sub0, n);                       // 2
    conv_fine_tiled<32, 32, 32><<<(n + 255) / 256, 256>>>(fB, fA, coors, w_sub1, n);  // 3
    // launch 4: PROFILED slot -> sub2
    conv_fine_tiled<32, 64, 16><<<(n + 127) / 128, 256>>>(fA, fB, coors, w_sub2, n);  // 4
    conv_fine_tiled<64, 64, 16><<<(n + 127) / 128, 256>>>(fB, fA, coors, w_sub3, n);  // 5
    mask_kernel<<<(n + 255) / 256, 256>>>(coors, maskp, n);                      // 6

    // down0: fine f32 -> coarse bf16 hi/lo
    conv_grid_tiled<64, 64, 16, FS, 27, 1><<<NC1 / 128, 256>>>(fA, nullptr, cAh, cAl, w_down0); // 7

    bprep_kernel<<<(27 * 64 * 96 + 255) / 256, 256>>>(w_sub4, b4h, b4l, 27 * 64 * 96);  // 8
    bprep_kernel<<<(27 * 96 * 96 + 255) / 256, 256>>>(w_sub5, b5h, b5l, 27 * 96 * 96);  // 9
    repack_kernel<<<(8 * 96 * 64 + 255) / 256, 256>>>(w_inv1, pwi1, 8, 96, 64);  // 10
    repack_kernel<<<(27 * 64 * 32 + 255) / 256, 256>>>(w_inv0, pwi0, 27, 64, 32);// 11

    conv_coarse_wmma<64, true><<<NC1 / 128, 256, SMEM4>>>(cAh, cAl, nullptr, cBh, cBl,
                                                          b4h, b4l, maskp);      // 12
    conv_coarse_wmma<96, false><<<NC1 / 128, 256, SMEM5>>>(cBh, cBl, cA, nullptr, nullptr,
                                                           b5h, b5l, maskp);     // 13

    conv_grid_tiled<96, 96, 8, CS, 8, 2><<<NC2 / 64, 192>>>(cA, c2p, nullptr, nullptr, w_down1); // 14

    inv1_kernel<<<NC1, 64>>>(c2p, cA, pwi1, maskp);                              // 15
    inv0_kernel<<<n, 32>>>(cA, (float*)d_out, coors, pwi0, n);                   // 16
}

// round 11
// speedup vs baseline: 1.5333x; 1.4672x over previous
#include <cuda_runtime.h>
#include <cuda_bf16.h>
#include <mma.h>
#include <cstdint>

using namespace nvcuda;

// ---------------- geometry ----------------
#define GD0 27
#define GH0 127
#define GW0 127
#define NVOX (GD0*GH0*GW0)        // 435483
#define GD1 14
#define GH1 64
#define GW1 64
#define NC1 (GD1*GH1*GW1)         // 57344
#define GD2 7
#define GH2 32
#define GW2 32
#define NC2 (GD2*GH2*GW2)         // 7168
#define FS 64
#define CS 96

// ---------------- static scratch (zero-init; inactive voxels never written) ----
__device__ float g_fineA[(size_t)NVOX * 4];               // scatter input (3ch used)
__device__ float g_cA[NC1 * CS];
__device__ float g_c2[NC2 * CS];
__device__ float g_mask[NC1];
__device__ float g_wi1[8 * 64 * 96];
__device__ float g_wi0[27 * 32 * 64];
// bf16 hi/lo fine activation buffers (stride FS)
__device__ __align__(256) __nv_bfloat16 g_fXh[(size_t)NVOX * FS];
__device__ __align__(256) __nv_bfloat16 g_fXl[(size_t)NVOX * FS];
__device__ __align__(256) __nv_bfloat16 g_fYh[(size_t)NVOX * FS];
__device__ __align__(256) __nv_bfloat16 g_fYl[(size_t)NVOX * FS];
// bf16 hi/lo coarse activation buffers
__device__ __align__(256) __nv_bfloat16 g_cAh[NC1 * CS];
__device__ __align__(256) __nv_bfloat16 g_cAl[NC1 * CS];
__device__ __align__(256) __nv_bfloat16 g_cBh[NC1 * CS];
__device__ __align__(256) __nv_bfloat16 g_cBl[NC1 * CS];
// bf16 hi/lo weight images, ORIGINAL [tap][ci][co] layout
__device__ __align__(256) __nv_bfloat16 g_b1h[27 * 32 * 32],  g_b1l[27 * 32 * 32];
__device__ __align__(256) __nv_bfloat16 g_b2h[27 * 32 * 64],  g_b2l[27 * 32 * 64];
__device__ __align__(256) __nv_bfloat16 g_b3h[27 * 64 * 64],  g_b3l[27 * 64 * 64];
__device__ __align__(256) __nv_bfloat16 g_bd0h[27 * 64 * 64], g_bd0l[27 * 64 * 64];
__device__ __align__(256) __nv_bfloat16 g_b4h[27 * 64 * 96],  g_b4l[27 * 64 * 96];
__device__ __align__(256) __nv_bfloat16 g_b5h[27 * 96 * 96],  g_b5l[27 * 96 * 96];

// ---------------- helpers ----------------
__device__ __forceinline__ void packpair(float x, float y, uint32_t& h, uint32_t& l) {
    __nv_bfloat16 hx = __float2bfloat16(x), hy = __float2bfloat16(y);
    __nv_bfloat16 lx = __float2bfloat16(x - __bfloat162float(hx));
    __nv_bfloat16 ly = __float2bfloat16(y - __bfloat162float(hy));
    __nv_bfloat162 hh; hh.x = hx; hh.y = hy;
    __nv_bfloat162 ll; ll.x = lx; ll.y = ly;
    h = *reinterpret_cast<uint32_t*>(&hh);
    l = *reinterpret_cast<uint32_t*>(&ll);
}

__global__ void bprep_kernel(const float* __restrict__ W, __nv_bfloat16* __restrict__ hi,
                             __nv_bfloat16* __restrict__ lo, int tot) {
    int i = blockIdx.x * blockDim.x + threadIdx.x;
    if (i >= tot) return;
    float v = W[i];
    __nv_bfloat16 h = __float2bfloat16(v);
    hi[i] = h;
    lo[i] = __float2bfloat16(v - __bfloat162float(h));
}

__global__ void repack_kernel(const float* __restrict__ w, float* __restrict__ o,
                              int k3, int cin, int cout) {
    int i = blockIdx.x * blockDim.x + threadIdx.x;
    int tot = k3 * cin * cout;
    if (i >= tot) return;
    int co = i % cout;
    int r  = i / cout;
    int ci = r % cin;
    int t  = r / cin;
    o[(t * cout + co) * cin + ci] = w[i];
}

__global__ void scatter_kernel(const float* __restrict__ f, const int* __restrict__ coors,
                               float* __restrict__ X, int n) {
    int p = blockIdx.x * blockDim.x + threadIdx.x;
    if (p >= n) return;
    int z = coors[p * 4 + 1], y = coors[p * 4 + 2], x = coors[p * 4 + 3];
    size_t vox = (size_t)((z * GH0 + y) * GW0 + x) * 4;
    X[vox + 0] = f[p * 3 + 0];
    X[vox + 1] = f[p * 3 + 1];
    X[vox + 2] = f[p * 3 + 2];
}

__global__ void mask_kernel(const int* __restrict__ coors, float* __restrict__ mask, int n) {
    int p = blockIdx.x * blockDim.x + threadIdx.x;
    if (p >= n) return;
    int z = coors[p * 4 + 1], y = coors[p * 4 + 2], x = coors[p * 4 + 3];
    int zo[2], yo[2], xo[2];
    int nzc = 0, nyc = 0, nxc = 0;
    if ((z & 1) == 0) { zo[nzc++] = z >> 1; }
    else { zo[nzc++] = z >> 1; if ((z >> 1) + 1 < GD1) zo[nzc++] = (z >> 1) + 1; }
    if ((y & 1) == 0) { yo[nyc++] = y >> 1; }
    else { yo[nyc++] = y >> 1; if ((y >> 1) + 1 < GH1) yo[nyc++] = (y >> 1) + 1; }
    if ((x & 1) == 0) { xo[nxc++] = x >> 1; }
    else { xo[nxc++] = x >> 1; if ((x >> 1) + 1 < GW1) xo[nxc++] = (x >> 1) + 1; }
    for (int a = 0; a < nzc; a++)
        for (int b = 0; b < nyc; b++)
            for (int c = 0; c < nxc; c++)
                mask[(zo[a] * GH1 + yo[b]) * GW1 + xo[c]] = 1.0f;
}

// ---------------- sub0: 3->32 per-point scalar; writes bf16 hi/lo
__global__ void __launch_bounds__(32) conv_sub0_kernel(
    const float* __restrict__ X, __nv_bfloat16* __restrict__ Yh,
    __nv_bfloat16* __restrict__ Yl,
    const int* __restrict__ coors, const float* __restrict__ W, int n) {
    __shared__ float xs[81];
    int p = blockIdx.x;
    if (p >= n) return;
    int z = coors[p * 4 + 1], y = coors[p * 4 + 2], x = coors[p * 4 + 3];
    int t = threadIdx.x;
    for (int i = t; i < 81; i += 32) {
        int tap = i / 3, ci = i % 3;
        int nz = z + tap / 9 - 1;
        int ny = y + (tap / 3) % 3 - 1;
        int nx = x + tap % 3 - 1;
        bool ok = (unsigned)nz < (unsigned)GD0 && (unsigned)ny < (unsigned)GH0 &&
                  (unsigned)nx < (unsigned)GW0;
        xs[i] = ok ? X[(size_t)((nz * GH0 + ny) * GW0 + nx) * 4 + ci] : 0.0f;
    }
    __syncthreads();
    float a = 0.f;
#pragma unroll
    for (int i = 0; i < 81; i++) a = fmaf(W[i * 32 + t], xs[i], a);
    size_t v = (size_t)((z * GH0 + y) * GW0 + x) * FS;
    __nv_bfloat16 h = __float2bfloat16(a);
    Yh[v + t] = h;
    Yl[v + t] = __float2bfloat16(a - __bfloat162float(h));
}

// ---------------- fine submanifold conv via wmma, bf16 hi/lo 3-term split
template <int CIN, int COUT>
__global__ void __launch_bounds__(256) conv_fine_wmma(
    const __nv_bfloat16* __restrict__ Xh, const __nv_bfloat16* __restrict__ Xl,
    __nv_bfloat16* __restrict__ Yh, __nv_bfloat16* __restrict__ Yl,
    const int* __restrict__ coors,
    const __nv_bfloat16* __restrict__ Bhi, const __nv_bfloat16* __restrict__ Blo, int n) {
    constexpr int LDA = CIN + 8;
    constexpr int LDB = COUT + 8;
    constexpr int KGA = CIN / 8;
    constexpr int NGB = COUT / 8;
    constexpr int BGN = CIN * NGB;
    constexpr int NT = COUT / 16;
    __shared__ int s_z[128], s_y[128], s_x[128];
    extern __shared__ __align__(256) char smem[];
    __nv_bfloat16* sAh = reinterpret_cast<__nv_bfloat16*>(smem);
    __nv_bfloat16* sAl = sAh + 128 * LDA;
    __nv_bfloat16* sBh = sAl + 128 * LDA;
    __nv_bfloat16* sBl = sBh + CIN * LDB;
    float* sOut = reinterpret_cast<float*>(smem);

    int tid = threadIdx.x, wid = tid >> 5;
    int p0 = blockIdx.x * 128;
    for (int i = tid; i < 128; i += 256) {
        int p = p0 + i;
        int zz = -8, yy = 0, xv = 0;
        if (p < n) { zz = coors[p * 4 + 1]; yy = coors[p * 4 + 2]; xv = coors[p * 4 + 3]; }
        s_z[i] = zz; s_y[i] = yy; s_x[i] = xv;
    }

    wmma::fragment<wmma::accumulator, 16, 16, 16, float> acc[NT];
#pragma unroll
    for (int i = 0; i < NT; i++) wmma::fill_fragment(acc[i], 0.0f);

    for (int tap = 0; tap < 27; tap++) {
        int dz = tap / 9 - 1, dy = (tap / 3) % 3 - 1, dx = tap % 3 - 1;
        __syncthreads();
        // stage B (padded)
        for (int j = tid; j < BGN; j += 256) {
            int ci = j / NGB, g = j - ci * NGB;
            const uint4* sh = reinterpret_cast<const uint4*>(
                Bhi + (size_t)tap * CIN * COUT + ci * COUT + g * 8);
            const uint4* sl = reinterpret_cast<const uint4*>(
                Blo + (size_t)tap * CIN * COUT + ci * COUT + g * 8);
            *reinterpret_cast<uint4*>(sBh + ci * LDB + g * 8) = *sh;
            *reinterpret_cast<uint4*>(sBl + ci * LDB + g * 8) = *sl;
        }
        // gather A (pure bf16 copy)
        for (int i = tid; i < 128 * KGA; i += 256) {
            int r = i / KGA, g = i - r * KGA;
            int k = g * 8;
            int nz = s_z[r] + dz, ny = s_y[r] + dy, nx = s_x[r] + dx;
            bool ok = (unsigned)nz < (unsigned)GD0 && (unsigned)ny < (unsigned)GH0 &&
                      (unsigned)nx < (unsigned)GW0;
            uint4 vh = make_uint4(0u, 0u, 0u, 0u), vl = vh;
            if (ok) {
                size_t base = (size_t)((nz * GH0 + ny) * GW0 + nx) * FS + k;
                vh = *reinterpret_cast<const uint4*>(Xh + base);
                vl = *reinterpret_cast<const uint4*>(Xl + base);
            }
            *reinterpret_cast<uint4*>(sAh + r * LDA + k) = vh;
            *reinterpret_cast<uint4*>(sAl + r * LDA + k) = vl;
        }
        __syncthreads();
        const __nv_bfloat16* ah = sAh + wid * 16 * LDA;
        const __nv_bfloat16* al = sAl + wid * 16 * LDA;
#pragma unroll
        for (int kt = 0; kt < CIN / 16; kt++) {
            wmma::fragment<wmma::matrix_a, 16, 16, 16, __nv_bfloat16, wmma::row_major> fah, fal;
            wmma::load_matrix_sync(fah, ah + kt * 16, LDA);
            wmma::load_matrix_sync(fal, al + kt * 16, LDA);
#pragma unroll
            for (int nt = 0; nt < NT; nt++) {
                wmma::fragment<wmma::matrix_b, 16, 16, 16, __nv_bfloat16, wmma::row_major> fbh, fbl;
                wmma::load_matrix_sync(fbh, sBh + kt * 16 * LDB + nt * 16, LDB);
                wmma::load_matrix_sync(fbl, sBl + kt * 16 * LDB + nt * 16, LDB);
                wmma::mma_sync(acc[nt], fah, fbh, acc[nt]);
                wmma::mma_sync(acc[nt], fah, fbl, acc[nt]);
                wmma::mma_sync(acc[nt], fal, fbh, acc[nt]);
            }
        }
    }
    __syncthreads();
#pragma unroll
    for (int nt = 0; nt < NT; nt++)
        wmma::store_matrix_sync(sOut + wid * 16 * COUT + nt * 16, acc[nt], COUT,
                                wmma::mem_row_major);
    __syncthreads();
    for (int i = tid; i < 128 * NGB; i += 256) {
        int r = i / NGB, g = i - r * NGB;
        int k = g * 8;
        int p = p0 + r;
        if (p >= n) continue;
        const float* s = sOut + r * COUT + k;
        float4 a = *reinterpret_cast<const float4*>(s);
        float4 b = *reinterpret_cast<const float4*>(s + 4);
        uint32_t h0, h1, h2, h3, l0, l1, l2, l3;
        packpair(a.x, a.y, h0, l0); packpair(a.z, a.w, h1, l1);
        packpair(b.x, b.y, h2, l2); packpair(b.z, b.w, h3, l3);
        size_t base = (size_t)((s_z[r] * GH0 + s_y[r]) * GW0 + s_x[r]) * FS + k;
        *reinterpret_cast<uint4*>(Yh + base) = make_uint4(h0, h1, h2, h3);
        *reinterpret_cast<uint4*>(Yl + base) = make_uint4(l0, l1, l2, l3);
    }
}

// ---------------- down0 via wmma: k=3,s=2,p=1, fine bf16 -> coarse bf16 hi/lo (dense)
__global__ void __launch_bounds__(256) conv_down0_wmma(
    const __nv_bfloat16* __restrict__ Xh, const __nv_bfloat16* __restrict__ Xl,
    __nv_bfloat16* __restrict__ Yh, __nv_bfloat16* __restrict__ Yl,
    const __nv_bfloat16* __restrict__ Bhi, const __nv_bfloat16* __restrict__ Blo) {
    constexpr int CIN = 64, COUT = 64;
    constexpr int LDA = CIN + 8;
    constexpr int LDB = COUT + 8;
    constexpr int KGA = CIN / 8;
    constexpr int NGB = COUT / 8;
    constexpr int BGN = CIN * NGB;
    constexpr int NT = COUT / 16;
    extern __shared__ __align__(256) char smem[];
    __nv_bfloat16* sAh = reinterpret_cast<__nv_bfloat16*>(smem);
    __nv_bfloat16* sAl = sAh + 128 * LDA;
    __nv_bfloat16* sBh = sAl + 128 * LDA;
    __nv_bfloat16* sBl = sBh + CIN * LDB;
    float* sOut = reinterpret_cast<float*>(smem);

    int tid = threadIdx.x, wid = tid >> 5;
    int o0 = blockIdx.x * 128;

    wmma::fragment<wmma::accumulator, 16, 16, 16, float> acc[NT];
#pragma unroll
    for (int i = 0; i < NT; i++) wmma::fill_fragment(acc[i], 0.0f);

    for (int tap = 0; tap < 27; tap++) {
        int dz = tap / 9 - 1, dy = (tap / 3) % 3 - 1, dx = tap % 3 - 1;
        __syncthreads();
        for (int j = tid; j < BGN; j += 256) {
            int ci = j / NGB, g = j - ci * NGB;
            const uint4* sh = reinterpret_cast<const uint4*>(
                Bhi + (size_t)tap * CIN * COUT + ci * COUT + g * 8);
            const uint4* sl = reinterpret_cast<const uint4*>(
                Blo + (size_t)tap * CIN * COUT + ci * COUT + g * 8);
            *reinterpret_cast<uint4*>(sBh + ci * LDB + g * 8) = *sh;
            *reinterpret_cast<uint4*>(sBl + ci * LDB + g * 8) = *sl;
        }
        for (int i = tid; i < 128 * KGA; i += 256) {
            int r = i / KGA, g = i - r * KGA;
            int k = g * 8;
            int o = o0 + r;
            int oz = o >> 12, oy = (o >> 6) & 63, ox = o & 63;
            int nz = 2 * oz + dz, ny = 2 * oy + dy, nx = 2 * ox + dx;
            bool ok = (unsigned)nz < (unsigned)GD0 && (unsigned)ny < (unsigned)GH0 &&
                      (unsigned)nx < (unsigned)GW0;
            uint4 vh = make_uint4(0u, 0u, 0u, 0u), vl = vh;
            if (ok) {
                size_t base = (size_t)((nz * GH0 + ny) * GW0 + nx) * FS + k;
                vh = *reinterpret_cast<const uint4*>(Xh + base);
                vl = *reinterpret_cast<const uint4*>(Xl + base);
            }
            *reinterpret_cast<uint4*>(sAh + r * LDA + k) = vh;
            *reinterpret_cast<uint4*>(sAl + r * LDA + k) = vl;
        }
        __syncthreads();
        const __nv_bfloat16* ah = sAh + wid * 16 * LDA;
        const __nv_bfloat16* al = sAl + wid * 16 * LDA;
#pragma unroll
        for (int kt = 0; kt < CIN / 16; kt++) {
            wmma::fragment<wmma::matrix_a, 16, 16, 16, __nv_bfloat16, wmma::row_major> fah, fal;
            wmma::load_matrix_sync(fah, ah + kt * 16, LDA);
            wmma::load_matrix_sync(fal, al + kt * 16, LDA);
#pragma unroll
            for (int nt = 0; nt < NT; nt++) {
                wmma::fragment<wmma::matrix_b, 16, 16, 16, __nv_bfloat16, wmma::row_major> fbh, fbl;
                wmma::load_matrix_sync(fbh, sBh + kt * 16 * LDB + nt * 16, LDB);
                wmma::load_matrix_sync(fbl, sBl + kt * 16 * LDB + nt * 16, LDB);
                wmma::mma_sync(acc[nt], fah, fbh, acc[nt]);
                wmma::mma_sync(acc[nt], fah, fbl, acc[nt]);
                wmma::mma_sync(acc[nt], fal, fbh, acc[nt]);
            }
        }
    }
    __syncthreads();
#pragma unroll
    for (int nt = 0; nt < NT; nt++)
        wmma::store_matrix_sync(sOut + wid * 16 * COUT + nt * 16, acc[nt], COUT,
                                wmma::mem_row_major);
    __syncthreads();
    for (int i = tid; i < 128 * NGB; i += 256) {
        int r = i / NGB, g = i - r * NGB;
        int k = g * 8;
        const float* s = sOut + r * COUT + k;
        float4 a = *reinterpret_cast<const float4*>(s);
        float4 b = *reinterpret_cast<const float4*>(s + 4);
        uint32_t h0, h1, h2, h3, l0, l1, l2, l3;
        packpair(a.x, a.y, h0, l0); packpair(a.z, a.w, h1, l1);
        packpair(b.x, b.y, h2, l2); packpair(b.z, b.w, h3, l3);
        size_t base = (size_t)(o0 + r) * CS + k;
        *reinterpret_cast<uint4*>(Yh + base) = make_uint4(h0, h1, h2, h3);
        *reinterpret_cast<uint4*>(Yl + base) = make_uint4(l0, l1, l2, l3);
    }
}

// ---------------- wmma coarse conv (k=3,s=1,p=1), masked, padded B
template <int CIN, bool OUT16>
__global__ void __launch_bounds__(256) conv_coarse_wmma(
    const __nv_bfloat16* __restrict__ Xh, const __nv_bfloat16* __restrict__ Xl,
    float* __restrict__ Yf, __nv_bfloat16* __restrict__ Yh, __nv_bfloat16* __restrict__ Yl,
    const __nv_bfloat16* __restrict__ Bhi, const __nv_bfloat16* __restrict__ Blo,
    const float* __restrict__ mask) {
    constexpr int COUT = 96;
    constexpr int LDA = CIN + 8;
    constexpr int LDB = COUT + 8;
    constexpr int KGA = CIN / 8;
    constexpr int NGB = COUT / 8;
    constexpr int BGN = CIN * NGB;
    extern __shared__ __align__(256) char smem[];
    __nv_bfloat16* sAh = reinterpret_cast<__nv_bfloat16*>(smem);
    __nv_bfloat16* sAl = sAh + 128 * LDA;
    __nv_bfloat16* sBh = sAl + 128 * LDA;
    __nv_bfloat16* sBl = sBh + CIN * LDB;
    float* sOut = reinterpret_cast<float*>(smem);

    int tid = threadIdx.x, wid = tid >> 5;
    int o0 = blockIdx.x * 128;

    wmma::fragment<wmma::accumulator, 16, 16, 16, float> acc[6];
#pragma unroll
    for (int i = 0; i < 6; i++) wmma::fill_fragment(acc[i], 0.0f);

    for (int tap = 0; tap < 27; tap++) {
        int dz = tap / 9 - 1, dy = (tap / 3) % 3 - 1, dx = tap % 3 - 1;
        __syncthreads();
        for (int j = tid; j < BGN; j += 256) {
            int ci = j / NGB, g = j - ci * NGB;
            const uint4* sh = reinterpret_cast<const uint4*>(
                Bhi + (size_t)tap * CIN * COUT + ci * COUT + g * 8);
            const uint4* sl = reinterpret_cast<const uint4*>(
                Blo + (size_t)tap * CIN * COUT + ci * COUT + g * 8);
            *reinterpret_cast<uint4*>(sBh + ci * LDB + g * 8) = *sh;
            *reinterpret_cast<uint4*>(sBl + ci * LDB + g * 8) = *sl;
        }
        for (int i = tid; i < 128 * KGA; i += 256) {
            int r = i / KGA, g = i - r * KGA;
            int k = g * 8;
            int o = o0 + r;
            int oz = o >> 12, oy = (o >> 6) & 63, ox = o & 63;
            int nz = oz + dz, ny = oy + dy, nx = ox + dx;
            bool ok = (unsigned)nz < (unsigned)GD1 && (unsigned)ny < (unsigned)GH1 &&
                      (unsigned)nx < (unsigned)GW1;
            uint4 vh = make_uint4(0u, 0u, 0u, 0u), vl = vh;
            if (ok) {
                size_t base = (size_t)((nz * GH1 + ny) * GW1 + nx) * CS + k;
                vh = *reinterpret_cast<const uint4*>(Xh + base);
                vl = *reinterpret_cast<const uint4*>(Xl + base);
            }
            *reinterpret_cast<uint4*>(sAh + r * LDA + k) = vh;
            *reinterpret_cast<uint4*>(sAl + r * LDA + k) = vl;
        }
        __syncthreads();
        const __nv_bfloat16* ah = sAh + wid * 16 * LDA;
        const __nv_bfloat16* al = sAl + wid * 16 * LDA;
#pragma unroll
        for (int kt = 0; kt < CIN / 16; kt++) {
            wmma::fragment<wmma::matrix_a, 16, 16, 16, __nv_bfloat16, wmma::row_major> fah, fal;
            wmma::load_matrix_sync(fah, ah + kt * 16, LDA);
            wmma::load_matrix_sync(fal, al + kt * 16, LDA);
#pragma unroll
            for (int nt = 0; nt < 6; nt++) {
                wmma::fragment<wmma::matrix_b, 16, 16, 16, __nv_bfloat16, wmma::row_major> fbh, fbl;
                wmma::load_matrix_sync(fbh, sBh + kt * 16 * LDB + nt * 16, LDB);
                wmma::load_matrix_sync(fbl, sBl + kt * 16 * LDB + nt * 16, LDB);
                wmma::mma_sync(acc[nt], fah, fbh, acc[nt]);
                wmma::mma_sync(acc[nt], fah, fbl, acc[nt]);
                wmma::mma_sync(acc[nt], fal, fbh, acc[nt]);
            }
        }
    }
    __syncthreads();
#pragma unroll
    for (int nt = 0; nt < 6; nt++)
        wmma::store_matrix_sync(sOut + wid * 16 * COUT + nt * 16, acc[nt], COUT,
                                wmma::mem_row_major);
    __syncthreads();
    if (OUT16) {
        for (int i = tid; i < 128 * 12; i += 256) {
            int r = i / 12, g = i - r * 12;
            int k = g * 8;
            float mv = mask[o0 + r];
            const float* s = sOut + r * COUT + k;
            float4 a = *reinterpret_cast<const float4*>(s);
            float4 b = *reinterpret_cast<const float4*>(s + 4);
            a.x *= mv; a.y *= mv; a.z *= mv; a.w *= mv;
            b.x *= mv; b.y *= mv; b.z *= mv; b.w *= mv;
            uint32_t h0, h1, h2, h3, l0, l1, l2, l3;
            packpair(a.x, a.y, h0, l0); packpair(a.z, a.w, h1, l1);
            packpair(b.x, b.y, h2, l2); packpair(b.z, b.w, h3, l3);
            size_t base = (size_t)(o0 + r) * CS + k;
            *reinterpret_cast<uint4*>(Yh + base) = make_uint4(h0, h1, h2, h3);
            *reinterpret_cast<uint4*>(Yl + base) = make_uint4(l0, l1, l2, l3);
        }
    } else {
        for (int i = tid; i < 128 * 24; i += 256) {
            int r = i / 24, c = i - r * 24;
            float mv = mask[o0 + r];
            float4 v = reinterpret_cast<const float4*>(sOut + r * COUT)[c];
            v.x *= mv; v.y *= mv; v.z *= mv; v.w *= mv;
            *reinterpret_cast<float4*>(&Yf[(size_t)(o0 + r) * CS + c * 4]) = v;
        }
    }
}

// ---------------- scalar leftovers: down1, inv1, inv0 ----------------
__device__ __forceinline__ void fma4(float4& a, float4 w, float x) {
    a.x = fmaf(w.x, x, a.x);
    a.y = fmaf(w.y, x, a.y);
    a.z = fmaf(w.z, x, a.z);
    a.w = fmaf(w.w, x, a.w);
}

template <int CIN>
__device__ __forceinline__ void dotrow4(const float* __restrict__ w,
                                        const float* __restrict__ xv, float4& a) {
#pragma unroll
    for (int c = 0; c < CIN; c += 4) {
        float4 wv = *reinterpret_cast<const float4*>(w + c);
        float4 x4 = *reinterpret_cast<const float4*>(xv + c);
        a.x = fmaf(wv.x, x4.x, a.x);
        a.y = fmaf(wv.y, x4.y, a.y);
        a.z = fmaf(wv.z, x4.z, a.z);
        a.w = fmaf(wv.w, x4.w, a.w);
    }
}

// down1: k=2, s=2, tiled scalar (f32 -> f32)
__global__ void __launch_bounds__(192) conv_down1_kernel(
    const float* __restrict__ X, float* __restrict__ Y, const float* __restrict__ Wt) {
    constexpr int CIN = 96, COUT = 96, TM = 8;
    constexpr int TC = COUT / 4;
    constexpr int THREADS = TC * TM;
    constexpr int MT = TM * 8;
    constexpr int XPAD = MT + 4;
    constexpr int C4 = CIN / 4;
    __shared__ __align__(16) float xs[CIN * XPAD];
    int t = threadIdx.x;
    int o0 = blockIdx.x * MT;
    float4 acc[8];
#pragma unroll
    for (int j = 0; j < 8; j++) acc[j] = make_float4(0.f, 0.f, 0.f, 0.f);
    int tc = t % TC, tm = t / TC;

    for (int tap = 0; tap < 8; tap++) {
        int dz = tap >> 2, dy = (tap >> 1) & 1, dx = tap & 1;
        __syncthreads();
        for (int i = t; i < MT * C4; i += THREADS) {
            int m = i / C4, c4 = i - m * C4;
            int o = o0 + m;
            int oz = o >> 10, oy = (o >> 5) & 31, ox = o & 31;
            int nz = 2 * oz + dz, ny = 2 * oy + dy, nx = 2 * ox + dx;
            size_t base = (size_t)((nz * GH1 + ny) * GW1 + nx) * CS;
            float4 v = *reinterpret_cast<const float4*>(&X[base + c4 * 4]);
            xs[(c4 * 4 + 0) * XPAD + m] = v.x;
            xs[(c4 * 4 + 1) * XPAD + m] = v.y;
            xs[(c4 * 4 + 2) * XPAD + m] = v.z;
            xs[(c4 * 4 + 3) * XPAD + m] = v.w;
        }
        __syncthreads();
        const float* wp = Wt + (size_t)tap * CIN * COUT + tc * 4;
#pragma unroll 8
        for (int ci = 0; ci < CIN; ci++) {
            float4 w4 = *reinterpret_cast<const float4*>(wp + ci * COUT);
            float4 xa = *reinterpret_cast<const float4*>(xs + ci * XPAD + tm * 8);
            float4 xb = *reinterpret_cast<const float4*>(xs + ci * XPAD + tm * 8 + 4);
            fma4(acc[0], w4, xa.x); fma4(acc[1], w4, xa.y);
            fma4(acc[2], w4, xa.z); fma4(acc[3], w4, xa.w);
            fma4(acc[4], w4, xb.x); fma4(acc[5], w4, xb.y);
            fma4(acc[6], w4, xb.z); fma4(acc[7], w4, xb.w);
        }
    }
#pragma unroll
    for (int j = 0; j < 8; j++) {
        int m = tm * 8 + j;
        *reinterpret_cast<float4*>(&Y[(size_t)(o0 + m) * CS + tc * 4]) = acc[j];
    }
}

__global__ void __launch_bounds__(64) inv1_kernel(
    const float* __restrict__ X2, float* __restrict__ Y,
    const float* __restrict__ Wt, const float* __restrict__ mask) {
    constexpr int CIN = 96;
    __shared__ __align__(16) float xs[CIN];
    int o = blockIdx.x;
    int t = threadIdx.x;
    float mv = mask[o];
    if (mv == 0.0f) { Y[o * CS + t] = 0.0f; return; }
    int oz = o >> 12, oy = (o >> 6) & 63, ox = o & 63;
    int m = (((oz >> 1) * GH2) + (oy >> 1)) * GW2 + (ox >> 1);
    int tap = ((oz & 1) * 2 + (oy & 1)) * 2 + (ox & 1);
    for (int c = t; c < CIN; c += 64) xs[c] = X2[(size_t)m * CS + c];
    __syncthreads();
    float4 acc = make_float4(0.f, 0.f, 0.f, 0.f);
    dotrow4<CIN>(Wt + (tap * 64 + t) * CIN, xs, acc);
    Y[o * CS + t] = (acc.x + acc.y + acc.z + acc.w) * mv;
}

__global__ void __launch_bounds__(32) inv0_kernel(
    const float* __restrict__ X, float* __restrict__ out,
    const int* __restrict__ coors, const float* __restrict__ Wt, int n) {
    constexpr int CIN = 64, COUT = 32;
    __shared__ __align__(16) float xs[CIN];
    int p = blockIdx.x;
    if (p >= n) return;
    int z = coors[p * 4 + 1], y = coors[p * 4 + 2], x = coors[p * 4 + 3];
    int t = threadIdx.x;

    int mzv[2], wzv[2], myv[2], wyv[2], mxv[2], wxv[2];
    int nzc = 0, nyc = 0, nxc = 0;
    if ((z & 1) == 0) { mzv[0] = z >> 1; wzv[0] = 1; nzc = 1; }
    else {
        mzv[nzc] = z >> 1; wzv[nzc] = 2; nzc++;
        if ((z >> 1) + 1 < GD1) { mzv[nzc] = (z >> 1) + 1; wzv[nzc] = 0; nzc++; }
    }
    if ((y & 1) == 0) { myv[0] = y >> 1; wyv[0] = 1; nyc = 1; }
    else {
        myv[nyc] = y >> 1; wyv[nyc] = 2; nyc++;
        if ((y >> 1) + 1 < GH1) { myv[nyc] = (y >> 1) + 1; wyv[nyc] = 0; nyc++; }
    }
    if ((x & 1) == 0) { mxv[0] = x >> 1; wxv[0] = 1; nxc = 1; }
    else {
        mxv[nxc] = x >> 1; wxv[nxc] = 2; nxc++;
        if ((x >> 1) + 1 < GW1) { mxv[nxc] = (x >> 1) + 1; wxv[nxc] = 0; nxc++; }
    }

    float4 acc = make_float4(0.f, 0.f, 0.f, 0.f);
    for (int a = 0; a < nzc; a++)
        for (int b = 0; b < nyc; b++)
            for (int c = 0; c < nxc; c++) {
                int m = ((mzv[a] * GH1) + myv[b]) * GW1 + mxv[c];
                int tap = (wzv[a] * 3 + wyv[b]) * 3 + wxv[c];
                xs[t] = X[(size_t)m * CS + t];
                xs[t + 32] = X[(size_t)m * CS + t + 32];
                __syncthreads();
                dotrow4<CIN>(Wt + (tap * COUT + t) * CIN, xs, acc);
                __syncthreads();
            }
    out[(size_t)p * COUT + t] = acc.x + acc.y + acc.z + acc.w;
}

// ---------------- launch ----------------
extern "C" void kernel_launch(void* const* d_in, const int* in_sizes, int n_in,
                              void* d_out, int out_size) {
    const float* features = (const float*)d_in[0];
    const int* coors      = (const int*)d_in[1];
    int wb = n_in - 10;
    const float* w_sub0  = (const float*)d_in[wb + 0];
    const float* w_sub1  = (const float*)d_in[wb + 1];
    const float* w_sub2  = (const float*)d_in[wb + 2];
    const float* w_sub3  = (const float*)d_in[wb + 3];
    const float* w_down0 = (const float*)d_in[wb + 4];
    const float* w_sub4  = (const float*)d_in[wb + 5];
    const float* w_sub5  = (const float*)d_in[wb + 6];
    const float* w_down1 = (const float*)d_in[wb + 7];
    const float* w_inv1  = (const float*)d_in[wb + 8];
    const float* w_inv0  = (const float*)d_in[wb + 9];

    int n = in_sizes[0] / 3;

    float *fA, *cA, *c2p, *maskp, *pwi1, *pwi0;
    __nv_bfloat16 *fXh, *fXl, *fYh, *fYl, *cAh, *cAl, *cBh, *cBl;
    __nv_bfloat16 *b1h, *b1l, *b2h, *b2l, *b3h, *b3l, *bd0h, *bd0l, *b4h, *b4l, *b5h, *b5l;
    cudaGetSymbolAddress((void**)&fA, g_fineA);
    cudaGetSymbolAddress((void**)&cA, g_cA);
    cudaGetSymbolAddress((void**)&c2p, g_c2);
    cudaGetSymbolAddress((void**)&maskp, g_mask);
    cudaGetSymbolAddress((void**)&pwi1, g_wi1);
    cudaGetSymbolAddress((void**)&pwi0, g_wi0);
    cudaGetSymbolAddress((void**)&fXh, g_fXh);
    cudaGetSymbolAddress((void**)&fXl, g_fXl);
    cudaGetSymbolAddress((void**)&fYh, g_fYh);
    cudaGetSymbolAddress((void**)&fYl, g_fYl);
    cudaGetSymbolAddress((void**)&cAh, g_cAh);
    cudaGetSymbolAddress((void**)&cAl, g_cAl);
    cudaGetSymbolAddress((void**)&cBh, g_cBh);
    cudaGetSymbolAddress((void**)&cBl, g_cBl);
    cudaGetSymbolAddress((void**)&b1h, g_b1h);  cudaGetSymbolAddress((void**)&b1l, g_b1l);
    cudaGetSymbolAddress((void**)&b2h, g_b2h);  cudaGetSymbolAddress((void**)&b2l, g_b2l);
    cudaGetSymbolAddress((void**)&b3h, g_b3h);  cudaGetSymbolAddress((void**)&b3l, g_b3l);
    cudaGetSymbolAddress((void**)&bd0h, g_bd0h); cudaGetSymbolAddress((void**)&bd0l, g_bd0l);
    cudaGetSymbolAddress((void**)&b4h, g_b4h);  cudaGetSymbolAddress((void**)&b4l, g_b4l);
    cudaGetSymbolAddress((void**)&b5h, g_b5h);  cudaGetSymbolAddress((void**)&b5l, g_b5l);

    // dynamic smem sizes (max of mainloop and f32 out-tile reuse)
    constexpr int SM_F3232 = 2 * 128 * 40 * 2 + 2 * 32 * 40 * 2;                    // 25600
    constexpr int SM_F3264 = 32768;                                                  // out tile
    constexpr int SM_F6464 = 2 * 128 * 72 * 2 + 2 * 64 * 72 * 2;                    // 55296
    constexpr int SM_C64   = 2 * 128 * 72 * 2 + 2 * 64 * 104 * 2;                   // 63488
    constexpr int SM_C96   = 2 * 128 * 104 * 2 + 2 * 96 * 104 * 2;                  // 93184
    cudaFuncSetAttribute(conv_fine_wmma<32, 32>, cudaFuncAttributeMaxDynamicSharedMemorySize, SM_F3232);
    cudaFuncSetAttribute(conv_fine_wmma<32, 64>, cudaFuncAttributeMaxDynamicSharedMemorySize, SM_F3264);
    cudaFuncSetAttribute(conv_fine_wmma<64, 64>, cudaFuncAttributeMaxDynamicSharedMemorySize, SM_F6464);
    cudaFuncSetAttribute(conv_down0_wmma, cudaFuncAttributeMaxDynamicSharedMemorySize, SM_F6464);
    cudaFuncSetAttribute(conv_coarse_wmma<64, true>, cudaFuncAttributeMaxDynamicSharedMemorySize, SM_C64);
    cudaFuncSetAttribute(conv_coarse_wmma<96, false>, cudaFuncAttributeMaxDynamicSharedMemorySize, SM_C96);

    int nb = (n + 127) / 128;

    scatter_kernel<<<(n + 255) / 256, 256>>>(features, coors, fA, n);                         // 1
    bprep_kernel<<<(27 * 32 * 32 + 255) / 256, 256>>>(w_sub1, b1h, b1l, 27 * 32 * 32);        // 2
    conv_sub0_kernel<<<n, 32>>>(fA, fXh, fXl, coors, w_sub0, n);                              // 3
    // launch 4: PROFILED slot
    conv_fine_wmma<32, 32><<<nb, 256, SM_F3232>>>(fXh, fXl, fYh, fYl, coors, b1h, b1l, n);    // 4
    bprep_kernel<<<(27 * 32 * 64 + 255) / 256, 256>>>(w_sub2, b2h, b2l, 27 * 32 * 64);        // 5
    conv_fine_wmma<32, 64><<<nb, 256, SM_F3264>>>(fYh, fYl, fXh, fXl, coors, b2h, b2l, n);    // 6
    bprep_kernel<<<(27 * 64 * 64 + 255) / 256, 256>>>(w_sub3, b3h, b3l, 27 * 64 * 64);        // 7
    conv_fine_wmma<64, 64><<<nb, 256, SM_F6464>>>(fXh, fXl, fYh, fYl, coors, b3h, b3l, n);    // 8
    mask_kernel<<<(n + 255) / 256, 256>>>(coors, maskp, n);                                   // 9
    bprep_kernel<<<(27 * 64 * 64 + 255) / 256, 256>>>(w_down0, bd0h, bd0l, 27 * 64 * 64);     // 10
    conv_down0_wmma<<<NC1 / 128, 256, SM_F6464>>>(fYh, fYl, cAh, cAl, bd0h, bd0l);            // 11
    bprep_kernel<<<(27 * 64 * 96 + 255) / 256, 256>>>(w_sub4, b4h, b4l, 27 * 64 * 96);        // 12
    bprep_kernel<<<(27 * 96 * 96 + 255) / 256, 256>>>(w_sub5, b5h, b5l, 27 * 96 * 96);        // 13
    conv_coarse_wmma<64, true><<<NC1 / 128, 256, SM_C64>>>(cAh, cAl, nullptr, cBh, cBl,
                                                           b4h, b4l, maskp);                  // 14
    conv_coarse_wmma<96, false><<<NC1 / 128, 256, SM_C96>>>(cBh, cBl, cA, nullptr, nullptr,
                                                            b5h, b5l, maskp);                 // 15
    conv_down1_kernel<<<NC2 / 64, 192>>>(cA, c2p, w_down1);                                   // 16
    repack_kernel<<<(8 * 96 * 64 + 255) / 256, 256>>>(w_inv1, pwi1, 8, 96, 64);               // 17
    repack_kernel<<<(27 * 64 * 32 + 255) / 256, 256>>>(w_inv0, pwi0, 27, 64, 32);             // 18
    inv1_kernel<<<NC1, 64>>>(c2p, cA, pwi1, maskp);                                           // 19
    inv0_kernel<<<n, 32>>>(cA, (float*)d_out, coors, pwi0, n);                                // 20
}

// round 12
// speedup vs baseline: 1.6277x; 1.0616x over previous
#include <cuda_runtime.h>
#include <cuda_bf16.h>
#include <mma.h>
#include <cstdint>

using namespace nvcuda;

// ---------------- geometry ----------------
#define GD0 27
#define GH0 127
#define GW0 127
#define NVOX (GD0*GH0*GW0)        // 435483
#define GD1 14
#define GH1 64
#define GW1 64
#define NC1 (GD1*GH1*GW1)         // 57344
#define GD2 7
#define GH2 32
#define GW2 32
#define NC2 (GD2*GH2*GW2)         // 7168
#define FS 64
#define CS 96

// ---------------- static scratch (zero-init; inactive voxels never written) ----
__device__ float g_fineA[(size_t)NVOX * 4];               // scatter input (3ch used)
__device__ float g_cA[NC1 * CS];
__device__ float g_c2[NC2 * CS];
__device__ float g_mask[NC1];
__device__ float g_wi0[27 * 32 * 64];
// bf16 hi/lo fine activation buffers (stride FS)
__device__ __align__(256) __nv_bfloat16 g_fXh[(size_t)NVOX * FS];
__device__ __align__(256) __nv_bfloat16 g_fXl[(size_t)NVOX * FS];
__device__ __align__(256) __nv_bfloat16 g_fYh[(size_t)NVOX * FS];
__device__ __align__(256) __nv_bfloat16 g_fYl[(size_t)NVOX * FS];
// bf16 hi/lo coarse activation buffers
__device__ __align__(256) __nv_bfloat16 g_cAh[NC1 * CS];
__device__ __align__(256) __nv_bfloat16 g_cAl[NC1 * CS];
__device__ __align__(256) __nv_bfloat16 g_cBh[NC1 * CS];
__device__ __align__(256) __nv_bfloat16 g_cBl[NC1 * CS];
// bf16 hi/lo weight images, ORIGINAL [tap][ci][co] layout
__device__ __align__(256) __nv_bfloat16 g_b1h[27 * 32 * 32],  g_b1l[27 * 32 * 32];
__device__ __align__(256) __nv_bfloat16 g_b2h[27 * 32 * 64],  g_b2l[27 * 32 * 64];
__device__ __align__(256) __nv_bfloat16 g_b3h[27 * 64 * 64],  g_b3l[27 * 64 * 64];
__device__ __align__(256) __nv_bfloat16 g_bd0h[27 * 64 * 64], g_bd0l[27 * 64 * 64];
__device__ __align__(256) __nv_bfloat16 g_b4h[27 * 64 * 96],  g_b4l[27 * 64 * 96];
__device__ __align__(256) __nv_bfloat16 g_b5h[27 * 96 * 96],  g_b5l[27 * 96 * 96];

// ---------------- helpers ----------------
__device__ __forceinline__ void packpair(float x, float y, uint32_t& h, uint32_t& l) {
    __nv_bfloat16 hx = __float2bfloat16(x), hy = __float2bfloat16(y);
    __nv_bfloat16 lx = __float2bfloat16(x - __bfloat162float(hx));
    __nv_bfloat16 ly = __float2bfloat16(y - __bfloat162float(hy));
    __nv_bfloat162 hh; hh.x = hx; hh.y = hy;
    __nv_bfloat162 ll; ll.x = lx; ll.y = ly;
    h = *reinterpret_cast<uint32_t*>(&hh);
    l = *reinterpret_cast<uint32_t*>(&ll);
}

__global__ void bprep_kernel(const float* __restrict__ W, __nv_bfloat16* __restrict__ hi,
                             __nv_bfloat16* __restrict__ lo, int tot) {
    int i = blockIdx.x * blockDim.x + threadIdx.x;
    if (i >= tot) return;
    float v = W[i];
    __nv_bfloat16 h = __float2bfloat16(v);
    hi[i] = h;
    lo[i] = __float2bfloat16(v - __bfloat162float(h));
}

__global__ void repack_kernel(const float* __restrict__ w, float* __restrict__ o,
                              int k3, int cin, int cout) {
    int i = blockIdx.x * blockDim.x + threadIdx.x;
    int tot = k3 * cin * cout;
    if (i >= tot) return;
    int co = i % cout;
    int r  = i / cout;
    int ci = r % cin;
    int t  = r / cin;
    o[(t * cout + co) * cin + ci] = w[i];
}

__global__ void scatter_kernel(const float* __restrict__ f, const int* __restrict__ coors,
                               float* __restrict__ X, int n) {
    int p = blockIdx.x * blockDim.x + threadIdx.x;
    if (p >= n) return;
    int z = coors[p * 4 + 1], y = coors[p * 4 + 2], x = coors[p * 4 + 3];
    size_t vox = (size_t)((z * GH0 + y) * GW0 + x) * 4;
    X[vox + 0] = f[p * 3 + 0];
    X[vox + 1] = f[p * 3 + 1];
    X[vox + 2] = f[p * 3 + 2];
}

__global__ void mask_kernel(const int* __restrict__ coors, float* __restrict__ mask, int n) {
    int p = blockIdx.x * blockDim.x + threadIdx.x;
    if (p >= n) return;
    int z = coors[p * 4 + 1], y = coors[p * 4 + 2], x = coors[p * 4 + 3];
    int zo[2], yo[2], xo[2];
    int nzc = 0, nyc = 0, nxc = 0;
    if ((z & 1) == 0) { zo[nzc++] = z >> 1; }
    else { zo[nzc++] = z >> 1; if ((z >> 1) + 1 < GD1) zo[nzc++] = (z >> 1) + 1; }
    if ((y & 1) == 0) { yo[nyc++] = y >> 1; }
    else { yo[nyc++] = y >> 1; if ((y >> 1) + 1 < GH1) yo[nyc++] = (y >> 1) + 1; }
    if ((x & 1) == 0) { xo[nxc++] = x >> 1; }
    else { xo[nxc++] = x >> 1; if ((x >> 1) + 1 < GW1) xo[nxc++] = (x >> 1) + 1; }
    for (int a = 0; a < nzc; a++)
        for (int b = 0; b < nyc; b++)
            for (int c = 0; c < nxc; c++)
                mask[(zo[a] * GH1 + yo[b]) * GW1 + xo[c]] = 1.0f;
}

// ---------------- sub0: 3->32, 8 points per block (one warp per point)
__global__ void __launch_bounds__(256) conv_sub0_kernel(
    const float* __restrict__ X, __nv_bfloat16* __restrict__ Yh,
    __nv_bfloat16* __restrict__ Yl,
    const int* __restrict__ coors, const float* __restrict__ W, int n) {
    __shared__ float xs[8][84];
    int g = threadIdx.x >> 5, t = threadIdx.x & 31;
    int p = blockIdx.x * 8 + g;
    if (p >= n) return;
    int z = coors[p * 4 + 1], y = coors[p * 4 + 2], x = coors[p * 4 + 3];
    for (int i = t; i < 81; i += 32) {
        int tap = i / 3, ci = i % 3;
        int nz = z + tap / 9 - 1;
        int ny = y + (tap / 3) % 3 - 1;
        int nx = x + tap % 3 - 1;
        bool ok = (unsigned)nz < (unsigned)GD0 && (unsigned)ny < (unsigned)GH0 &&
                  (unsigned)nx < (unsigned)GW0;
        xs[g][i] = ok ? X[(size_t)((nz * GH0 + ny) * GW0 + nx) * 4 + ci] : 0.0f;
    }
    __syncwarp();
    float a = 0.f;
#pragma unroll
    for (int i = 0; i < 81; i++) a = fmaf(W[i * 32 + t], xs[g][i], a);
    size_t v = (size_t)((z * GH0 + y) * GW0 + x) * FS;
    __nv_bfloat16 h = __float2bfloat16(a);
    Yh[v + t] = h;
    Yl[v + t] = __float2bfloat16(a - __bfloat162float(h));
}

// ---------------- fine submanifold conv via wmma, bf16 hi/lo 3-term split
template <int CIN, int COUT, int MTILE>
__global__ void __launch_bounds__(MTILE * 2) conv_fine_wmma(
    const __nv_bfloat16* __restrict__ Xh, const __nv_bfloat16* __restrict__ Xl,
    __nv_bfloat16* __restrict__ Yh, __nv_bfloat16* __restrict__ Yl,
    const int* __restrict__ coors,
    const __nv_bfloat16* __restrict__ Bhi, const __nv_bfloat16* __restrict__ Blo, int n) {
    constexpr int THREADS = MTILE * 2;
    constexpr int LDA = CIN + 8;
    constexpr int LDB = COUT + 8;
    constexpr int KGA = CIN / 8;
    constexpr int NGB = COUT / 8;
    constexpr int BGN = CIN * NGB;
    constexpr int NT = COUT / 16;
    __shared__ int s_z[MTILE], s_y[MTILE], s_x[MTILE];
    extern __shared__ __align__(256) char smem[];
    __nv_bfloat16* sAh = reinterpret_cast<__nv_bfloat16*>(smem);
    __nv_bfloat16* sAl = sAh + MTILE * LDA;
    __nv_bfloat16* sBh = sAl + MTILE * LDA;
    __nv_bfloat16* sBl = sBh + CIN * LDB;
    float* sOut = reinterpret_cast<float*>(smem);

    int tid = threadIdx.x, wid = tid >> 5;
    int p0 = blockIdx.x * MTILE;
    for (int i = tid; i < MTILE; i += THREADS) {
        int p = p0 + i;
        int zz = -8, yy = 0, xv = 0;
        if (p < n) { zz = coors[p * 4 + 1]; yy = coors[p * 4 + 2]; xv = coors[p * 4 + 3]; }
        s_z[i] = zz; s_y[i] = yy; s_x[i] = xv;
    }

    wmma::fragment<wmma::accumulator, 16, 16, 16, float> acc[NT];
#pragma unroll
    for (int i = 0; i < NT; i++) wmma::fill_fragment(acc[i], 0.0f);

    for (int tap = 0; tap < 27; tap++) {
        int dz = tap / 9 - 1, dy = (tap / 3) % 3 - 1, dx = tap % 3 - 1;
        __syncthreads();
        for (int j = tid; j < BGN; j += THREADS) {
            int ci = j / NGB, g = j - ci * NGB;
            const uint4* sh = reinterpret_cast<const uint4*>(
                Bhi + (size_t)tap * CIN * COUT + ci * COUT + g * 8);
            const uint4* sl = reinterpret_cast<const uint4*>(
                Blo + (size_t)tap * CIN * COUT + ci * COUT + g * 8);
            *reinterpret_cast<uint4*>(sBh + ci * LDB + g * 8) = *sh;
            *reinterpret_cast<uint4*>(sBl + ci * LDB + g * 8) = *sl;
        }
        for (int i = tid; i < MTILE * KGA; i += THREADS) {
            int r = i / KGA, g = i - r * KGA;
            int k = g * 8;
            int nz = s_z[r] + dz, ny = s_y[r] + dy, nx = s_x[r] + dx;
            bool ok = (unsigned)nz < (unsigned)GD0 && (unsigned)ny < (unsigned)GH0 &&
                      (unsigned)nx < (unsigned)GW0;
            uint4 vh = make_uint4(0u, 0u, 0u, 0u), vl = vh;
            if (ok) {
                size_t base = (size_t)((nz * GH0 + ny) * GW0 + nx) * FS + k;
                vh = *reinterpret_cast<const uint4*>(Xh + base);
                vl = *reinterpret_cast<const uint4*>(Xl + base);
            }
            *reinterpret_cast<uint4*>(sAh + r * LDA + k) = vh;
            *reinterpret_cast<uint4*>(sAl + r * LDA + k) = vl;
        }
        __syncthreads();
        const __nv_bfloat16* ah = sAh + wid * 16 * LDA;
        const __nv_bfloat16* al = sAl + wid * 16 * LDA;
#pragma unroll
        for (int kt = 0; kt < CIN / 16; kt++) {
            wmma::fragment<wmma::matrix_a, 16, 16, 16, __nv_bfloat16, wmma::row_major> fah, fal;
            wmma::load_matrix_sync(fah, ah + kt * 16, LDA);
            wmma::load_matrix_sync(fal, al + kt * 16, LDA);
#pragma unroll
            for (int nt = 0; nt < NT; nt++) {
                wmma::fragment<wmma::matrix_b, 16, 16, 16, __nv_bfloat16, wmma::row_major> fbh, fbl;
                wmma::load_matrix_sync(fbh, sBh + kt * 16 * LDB + nt * 16, LDB);
                wmma::load_matrix_sync(fbl, sBl + kt * 16 * LDB + nt * 16, LDB);
                wmma::mma_sync(acc[nt], fah, fbh, acc[nt]);
                wmma::mma_sync(acc[nt], fah, fbl, acc[nt]);
                wmma::mma_sync(acc[nt], fal, fbh, acc[nt]);
            }
        }
    }
    __syncthreads();
#pragma unroll
    for (int nt = 0; nt < NT; nt++)
        wmma::store_matrix_sync(sOut + wid * 16 * COUT + nt * 16, acc[nt], COUT,
                                wmma::mem_row_major);
    __syncthreads();
    for (int i = tid; i < MTILE * NGB; i += THREADS) {
        int r = i / NGB, g = i - r * NGB;
        int k = g * 8;
        int p = p0 + r;
        if (p >= n) continue;
        const float* s = sOut + r * COUT + k;
        float4 a = *reinterpret_cast<const float4*>(s);
        float4 b = *reinterpret_cast<const float4*>(s + 4);
        uint32_t h0, h1, h2, h3, l0, l1, l2, l3;
        packpair(a.x, a.y, h0, l0); packpair(a.z, a.w, h1, l1);
        packpair(b.x, b.y, h2, l2); packpair(b.z, b.w, h3, l3);
        size_t base = (size_t)((s_z[r] * GH0 + s_y[r]) * GW0 + s_x[r]) * FS + k;
        *reinterpret_cast<uint4*>(Yh + base) = make_uint4(h0, h1, h2, h3);
        *reinterpret_cast<uint4*>(Yl + base) = make_uint4(l0, l1, l2, l3);
    }
}

// ---------------- down0 via wmma: k=3,s=2,p=1, fine bf16 -> coarse bf16 hi/lo (dense)
__global__ void __launch_bounds__(256) conv_down0_wmma(
    const __nv_bfloat16* __restrict__ Xh, const __nv_bfloat16* __restrict__ Xl,
    __nv_bfloat16* __restrict__ Yh, __nv_bfloat16* __restrict__ Yl,
    const __nv_bfloat16* __restrict__ Bhi, const __nv_bfloat16* __restrict__ Blo) {
    constexpr int CIN = 64, COUT = 64;
    constexpr int LDA = CIN + 8;
    constexpr int LDB = COUT + 8;
    constexpr int KGA = CIN / 8;
    constexpr int NGB = COUT / 8;
    constexpr int BGN = CIN * NGB;
    constexpr int NT = COUT / 16;
    extern __shared__ __align__(256) char smem[];
    __nv_bfloat16* sAh = reinterpret_cast<__nv_bfloat16*>(smem);
    __nv_bfloat16* sAl = sAh + 128 * LDA;
    __nv_bfloat16* sBh = sAl + 128 * LDA;
    __nv_bfloat16* sBl = sBh + CIN * LDB;
    float* sOut = reinterpret_cast<float*>(smem);

    int tid = threadIdx.x, wid = tid >> 5;
    int o0 = blockIdx.x * 128;

    wmma::fragment<wmma::accumulator, 16, 16, 16, float> acc[NT];
#pragma unroll
    for (int i = 0; i < NT; i++) wmma::fill_fragment(acc[i], 0.0f);

    for (int tap = 0; tap < 27; tap++) {
        int dz = tap / 9 - 1, dy = (tap / 3) % 3 - 1, dx = tap % 3 - 1;
        __syncthreads();
        for (int j = tid; j < BGN; j += 256) {
            int ci = j / NGB, g = j - ci * NGB;
            const uint4* sh = reinterpret_cast<const uint4*>(
                Bhi + (size_t)tap * CIN * COUT + ci * COUT + g * 8);
            const uint4* sl = reinterpret_cast<const uint4*>(
                Blo + (size_t)tap * CIN * COUT + ci * COUT + g * 8);
            *reinterpret_cast<uint4*>(sBh + ci * LDB + g * 8) = *sh;
            *reinterpret_cast<uint4*>(sBl + ci * LDB + g * 8) = *sl;
        }
        for (int i = tid; i < 128 * KGA; i += 256) {
            int r = i / KGA, g = i - r * KGA;
            int k = g * 8;
            int o = o0 + r;
            int oz = o >> 12, oy = (o >> 6) & 63, ox = o & 63;
            int nz = 2 * oz + dz, ny = 2 * oy + dy, nx = 2 * ox + dx;
            bool ok = (unsigned)nz < (unsigned)GD0 && (unsigned)ny < (unsigned)GH0 &&
                      (unsigned)nx < (unsigned)GW0;
            uint4 vh = make_uint4(0u, 0u, 0u, 0u), vl = vh;
            if (ok) {
                size_t base = (size_t)((nz * GH0 + ny) * GW0 + nx) * FS + k;
                vh = *reinterpret_cast<const uint4*>(Xh + base);
                vl = *reinterpret_cast<const uint4*>(Xl + base);
            }
            *reinterpret_cast<uint4*>(sAh + r * LDA + k) = vh;
            *reinterpret_cast<uint4*>(sAl + r * LDA + k) = vl;
        }
        __syncthreads();
        const __nv_bfloat16* ah = sAh + wid * 16 * LDA;
        const __nv_bfloat16* al = sAl + wid * 16 * LDA;
#pragma unroll
        for (int kt = 0; kt < CIN / 16; kt++) {
            wmma::fragment<wmma::matrix_a, 16, 16, 16, __nv_bfloat16, wmma::row_major> fah, fal;
            wmma::load_matrix_sync(fah, ah + kt * 16, LDA);
            wmma::load_matrix_sync(fal, al + kt * 16, LDA);
#pragma unroll
            for (int nt = 0; nt < NT; nt++) {
                wmma::fragment<wmma::matrix_b, 16, 16, 16, __nv_bfloat16, wmma::row_major> fbh, fbl;
                wmma::load_matrix_sync(fbh, sBh + kt * 16 * LDB + nt * 16, LDB);
                wmma::load_matrix_sync(fbl, sBl + kt * 16 * LDB + nt * 16, LDB);
                wmma::mma_sync(acc[nt], fah, fbh, acc[nt]);
                wmma::mma_sync(acc[nt], fah, fbl, acc[nt]);
                wmma::mma_sync(acc[nt], fal, fbh, acc[nt]);
            }
        }
    }
    __syncthreads();
#pragma unroll
    for (int nt = 0; nt < NT; nt++)
        wmma::store_matrix_sync(sOut + wid * 16 * COUT + nt * 16, acc[nt], COUT,
                                wmma::mem_row_major);
    __syncthreads();
    for (int i = tid; i < 128 * NGB; i += 256) {
        int r = i / NGB, g = i - r * NGB;
        int k = g * 8;
        const float* s = sOut + r * COUT + k;
        float4 a = *reinterpret_cast<const float4*>(s);
        float4 b = *reinterpret_cast<const float4*>(s + 4);
        uint32_t h0, h1, h2, h3, l0, l1, l2, l3;
        packpair(a.x, a.y, h0, l0); packpair(a.z, a.w, h1, l1);
        packpair(b.x, b.y, h2, l2); packpair(b.z, b.w, h3, l3);
        size_t base = (size_t)(o0 + r) * CS + k;
        *reinterpret_cast<uint4*>(Yh + base) = make_uint4(h0, h1, h2, h3);
        *reinterpret_cast<uint4*>(Yl + base) = make_uint4(l0, l1, l2, l3);
    }
}

// ---------------- wmma coarse conv (k=3,s=1,p=1), masked, padded B
template <int CIN, bool OUT16>
__global__ void __launch_bounds__(256) conv_coarse_wmma(
    const __nv_bfloat16* __restrict__ Xh, const __nv_bfloat16* __restrict__ Xl,
    float* __restrict__ Yf, __nv_bfloat16* __restrict__ Yh, __nv_bfloat16* __restrict__ Yl,
    const __nv_bfloat16* __restrict__ Bhi, const __nv_bfloat16* __restrict__ Blo,
    const float* __restrict__ mask) {
    constexpr int COUT = 96;
    constexpr int LDA = CIN + 8;
    constexpr int LDB = COUT + 8;
    constexpr int KGA = CIN / 8;
    constexpr int NGB = COUT / 8;
    constexpr int BGN = CIN * NGB;
    extern __shared__ __align__(256) char smem[];
    __nv_bfloat16* sAh = reinterpret_cast<__nv_bfloat16*>(smem);
    __nv_bfloat16* sAl = sAh + 128 * LDA;
    __nv_bfloat16* sBh = sAl + 128 * LDA;
    __nv_bfloat16* sBl = sBh + CIN * LDB;
    float* sOut = reinterpret_cast<float*>(smem);

    int tid = threadIdx.x, wid = tid >> 5;
    int o0 = blockIdx.x * 128;

    wmma::fragment<wmma::accumulator, 16, 16, 16, float> acc[6];
#pragma unroll
    for (int i = 0; i < 6; i++) wmma::fill_fragment(acc[i], 0.0f);

    for (int tap = 0; tap < 27; tap++) {
        int dz = tap / 9 - 1, dy = (tap / 3) % 3 - 1, dx = tap % 3 - 1;
        __syncthreads();
        for (int j = tid; j < BGN; j += 256) {
            int ci = j / NGB, g = j - ci * NGB;
            const uint4* sh = reinterpret_cast<const uint4*>(
                Bhi + (size_t)tap * CIN * COUT + ci * COUT + g * 8);
            const uint4* sl = reinterpret_cast<const uint4*>(
                Blo + (size_t)tap * CIN * COUT + ci * COUT + g * 8);
            *reinterpret_cast<uint4*>(sBh + ci * LDB + g * 8) = *sh;
            *reinterpret_cast<uint4*>(sBl + ci * LDB + g * 8) = *sl;
        }
        for (int i = tid; i < 128 * KGA; i += 256) {
            int r = i / KGA, g = i - r * KGA;
            int k = g * 8;
            int o = o0 + r;
            int oz = o >> 12, oy = (o >> 6) & 63, ox = o & 63;
            int nz = oz + dz, ny = oy + dy, nx = ox + dx;
            bool ok = (unsigned)nz < (unsigned)GD1 && (unsigned)ny < (unsigned)GH1 &&
                      (unsigned)nx < (unsigned)GW1;
            uint4 vh = make_uint4(0u, 0u, 0u, 0u), vl = vh;
            if (ok) {
                size_t base = (size_t)((nz * GH1 + ny) * GW1 + nx) * CS + k;
                vh = *reinterpret_cast<const uint4*>(Xh + base);
                vl = *reinterpret_cast<const uint4*>(Xl + base);
            }
            *reinterpret_cast<uint4*>(sAh + r * LDA + k) = vh;
            *reinterpret_cast<uint4*>(sAl + r * LDA + k) = vl;
        }
        __syncthreads();
        const __nv_bfloat16* ah = sAh + wid * 16 * LDA;
        const __nv_bfloat16* al = sAl + wid * 16 * LDA;
#pragma unroll
        for (int kt = 0; kt < CIN / 16; kt++) {
            wmma::fragment<wmma::matrix_a, 16, 16, 16, __nv_bfloat16, wmma::row_major> fah, fal;
            wmma::load_matrix_sync(fah, ah + kt * 16, LDA);
            wmma::load_matrix_sync(fal, al + kt * 16, LDA);
#pragma unroll
            for (int nt = 0; nt < 6; nt++) {
                wmma::fragment<wmma::matrix_b, 16, 16, 16, __nv_bfloat16, wmma::row_major> fbh, fbl;
                wmma::load_matrix_sync(fbh, sBh + kt * 16 * LDB + nt * 16, LDB);
                wmma::load_matrix_sync(fbl, sBl + kt * 16 * LDB + nt * 16, LDB);
                wmma::mma_sync(acc[nt], fah, fbh, acc[nt]);
                wmma::mma_sync(acc[nt], fah, fbl, acc[nt]);
                wmma::mma_sync(acc[nt], fal, fbh, acc[nt]);
            }
        }
    }
    __syncthreads();
#pragma unroll
    for (int nt = 0; nt < 6; nt++)
        wmma::store_matrix_sync(sOut + wid * 16 * COUT + nt * 16, acc[nt], COUT,
                                wmma::mem_row_major);
    __syncthreads();
    if (OUT16) {
        for (int i = tid; i < 128 * 12; i += 256) {
            int r = i / 12, g = i - r * 12;
            int k = g * 8;
            float mv = mask[o0 + r];
            const float* s = sOut + r * COUT + k;
            float4 a = *reinterpret_cast<const float4*>(s);
            float4 b = *reinterpret_cast<const float4*>(s + 4);
            a.x *= mv; a.y *= mv; a.z *= mv; a.w *= mv;
            b.x *= mv; b.y *= mv; b.z *= mv; b.w *= mv;
            uint32_t h0, h1, h2, h3, l0, l1, l2, l3;
            packpair(a.x, a.y, h0, l0); packpair(a.z, a.w, h1, l1);
            packpair(b.x, b.y, h2, l2); packpair(b.z, b.w, h3, l3);
            size_t base = (size_t)(o0 + r) * CS + k;
            *reinterpret_cast<uint4*>(Yh + base) = make_uint4(h0, h1, h2, h3);
            *reinterpret_cast<uint4*>(Yl + base) = make_uint4(l0, l1, l2, l3);
        }
    } else {
        for (int i = tid; i < 128 * 24; i += 256) {
            int r = i / 24, c = i - r * 24;
            float mv = mask[o0 + r];
            float4 v = reinterpret_cast<const float4*>(sOut + r * COUT)[c];
            v.x *= mv; v.y *= mv; v.z *= mv; v.w *= mv;
            *reinterpret_cast<float4*>(&Yf[(size_t)(o0 + r) * CS + c * 4]) = v;
        }
    }
}

// ---------------- scalar decoder ----------------
__device__ __forceinline__ void fma4(float4& a, float4 w, float x) {
    a.x = fmaf(w.x, x, a.x);
    a.y = fmaf(w.y, x, a.y);
    a.z = fmaf(w.z, x, a.z);
    a.w = fmaf(w.w, x, a.w);
}

template <int CIN>
__device__ __forceinline__ void dotrow4(const float* __restrict__ w,
                                        const float* __restrict__ xv, float4& a) {
#pragma unroll
    for (int c = 0; c < CIN; c += 4) {
        float4 wv = *reinterpret_cast<const float4*>(w + c);
        float4 x4 = *reinterpret_cast<const float4*>(xv + c);
        a.x = fmaf(wv.x, x4.x, a.x);
        a.y = fmaf(wv.y, x4.y, a.y);
        a.z = fmaf(wv.z, x4.z, a.z);
        a.w = fmaf(wv.w, x4.w, a.w);
    }
}

// down1: k=2, s=2, tiled scalar (f32 -> f32)
__global__ void __launch_bounds__(192) conv_down1_kernel(
    const float* __restrict__ X, float* __restrict__ Y, const float* __restrict__ Wt) {
    constexpr int CIN = 96, COUT = 96, TM = 8;
    constexpr int TC = COUT / 4;
    constexpr int THREADS = TC * TM;
    constexpr int MT = TM * 8;
    constexpr int XPAD = MT + 4;
    constexpr int C4 = CIN / 4;
    __shared__ __align__(16) float xs[CIN * XPAD];
    int t = threadIdx.x;
    int o0 = blockIdx.x * MT;
    float4 acc[8];
#pragma unroll
    for (int j = 0; j < 8; j++) acc[j] = make_float4(0.f, 0.f, 0.f, 0.f);
    int tc = t % TC, tm = t / TC;

    for (int tap = 0; tap < 8; tap++) {
        int dz = tap >> 2, dy = (tap >> 1) & 1, dx = tap & 1;
        __syncthreads();
        for (int i = t; i < MT * C4; i += THREADS) {
            int m = i / C4, c4 = i - m * C4;
            int o = o0 + m;
            int oz = o >> 10, oy = (o >> 5) & 31, ox = o & 31;
            int nz = 2 * oz + dz, ny = 2 * oy + dy, nx = 2 * ox + dx;
            size_t base = (size_t)((nz * GH1 + ny) * GW1 + nx) * CS;
            float4 v = *reinterpret_cast<const float4*>(&X[base + c4 * 4]);
            xs[(c4 * 4 + 0) * XPAD + m] = v.x;
            xs[(c4 * 4 + 1) * XPAD + m] = v.y;
            xs[(c4 * 4 + 2) * XPAD + m] = v.z;
            xs[(c4 * 4 + 3) * XPAD + m] = v.w;
        }
        __syncthreads();
        const float* wp = Wt + (size_t)tap * CIN * COUT + tc * 4;
#pragma unroll 8
        for (int ci = 0; ci < CIN; ci++) {
            float4 w4 = *reinterpret_cast<const float4*>(wp + ci * COUT);
            float4 xa = *reinterpret_cast<const float4*>(xs + ci * XPAD + tm * 8);
            float4 xb = *reinterpret_cast<const float4*>(xs + ci * XPAD + tm * 8 + 4);
            fma4(acc[0], w4, xa.x); fma4(acc[1], w4, xa.y);
            fma4(acc[2], w4, xa.z); fma4(acc[3], w4, xa.w);
            fma4(acc[4], w4, xb.x); fma4(acc[5], w4, xb.y);
            fma4(acc[6], w4, xb.z); fma4(acc[7], w4, xb.w);
        }
    }
#pragma unroll
    for (int j = 0; j < 8; j++) {
        int m = tm * 8 + j;
        *reinterpret_cast<float4*>(&Y[(size_t)(o0 + m) * CS + tc * 4]) = acc[j];
    }
}

// inv1 tiled: block = one x-row of 64 outputs; 2 taps selected by x parity.
// Weights in ORIGINAL layout (2,2,2,96,64).
__global__ void __launch_bounds__(128) inv1_tiled_kernel(
    const float* __restrict__ X2, float* __restrict__ Y,
    const float* __restrict__ W, const float* __restrict__ mask) {
    constexpr int SPAD = 33;
    __shared__ __align__(16) float xs[96 * SPAD];
    int t = threadIdx.x;
    int o0 = blockIdx.x * 64;
    int oz = o0 >> 12, oy = (o0 >> 6) & 63;
    int m0 = (((oz >> 1) * GH2) + (oy >> 1)) * GW2;   // 32 sources along x
    int tapBase = ((oz & 1) * 2 + (oy & 1)) * 2;

    // stage 32 sources x 96 channels
    for (int i = t; i < 32 * 24; i += 128) {
        int s = i / 24, c4 = i - s * 24;
        float4 v = *reinterpret_cast<const float4*>(&X2[(size_t)(m0 + s) * CS + c4 * 4]);
        xs[(c4 * 4 + 0) * SPAD + s] = v.x;
        xs[(c4 * 4 + 1) * SPAD + s] = v.y;
        xs[(c4 * 4 + 2) * SPAD + s] = v.z;
        xs[(c4 * 4 + 3) * SPAD + s] = v.w;
    }
    __syncthreads();

    int tc = t & 15, tm = t >> 4;      // tc: 16 cout groups of 4; tm: 8 output groups of 8
    const float* wE = W + (size_t)tapBase * 96 * 64 + tc * 4;
    const float* wO = wE + 96 * 64;
    float4 acc[8];
#pragma unroll
    for (int j = 0; j < 8; j++) acc[j] = make_float4(0.f, 0.f, 0.f, 0.f);
#pragma unroll 4
    for (int ci = 0; ci < 96; ci++) {
        float4 we = *reinterpret_cast<const float4*>(wE + ci * 64);
        float4 wo = *reinterpret_cast<const float4*>(wO + ci * 64);
        float x0 = xs[ci * SPAD + tm * 4 + 0];
        float x1 = xs[ci * SPAD + tm * 4 + 1];
        float x2 = xs[ci * SPAD + tm * 4 + 2];
        float x3 = xs[ci * SPAD + tm * 4 + 3];
        fma4(acc[0], we, x0); fma4(acc[1], wo, x0);
        fma4(acc[2], we, x1); fma4(acc[3], wo, x1);
        fma4(acc[4], we, x2); fma4(acc[5], wo, x2);
        fma4(acc[6], we, x3); fma4(acc[7], wo, x3);
    }
#pragma unroll
    for (int j = 0; j < 8; j++) {
        int o = o0 + tm * 8 + j;
        float mv = mask[o];
        float4 r = acc[j];
        r.x *= mv; r.y *= mv; r.z *= mv; r.w *= mv;
        *reinterpret_cast<float4*>(&Y[(size_t)o * CS + tc * 4]) = r;
    }
}

// inv0: 8 points per block, one warp per point (repacked weights [tap][cout][cin])
__global__ void __launch_bounds__(256) inv0_kernel(
    const float* __restrict__ X, float* __restrict__ out,
    const int* __restrict__ coors, const float* __restrict__ Wt, int n) {
    constexpr int CIN = 64, COUT = 32;
    __shared__ __align__(16) float xs[8][CIN];
    int g = threadIdx.x >> 5, t = threadIdx.x & 31;
    int p = blockIdx.x * 8 + g;
    if (p >= n) return;
    int z = coors[p * 4 + 1], y = coors[p * 4 + 2], x = coors[p * 4 + 3];

    int mzv[2], wzv[2], myv[2], wyv[2], mxv[2], wxv[2];
    int nzc = 0, nyc = 0, nxc = 0;
    if ((z & 1) == 0) { mzv[0] = z >> 1; wzv[0] = 1; nzc = 1; }
    else {
        mzv[nzc] = z >> 1; wzv[nzc] = 2; nzc++;
        if ((z >> 1) + 1 < GD1) { mzv[nzc] = (z >> 1) + 1; wzv[nzc] = 0; nzc++; }
    }
    if ((y & 1) == 0) { myv[0] = y >> 1; wyv[0] = 1; nyc = 1; }
    else {
        myv[nyc] = y >> 1; wyv[nyc] = 2; nyc++;
        if ((y >> 1) + 1 < GH1) { myv[nyc] = (y >> 1) + 1; wyv[nyc] = 0; nyc++; }
    }
    if ((x & 1) == 0) { mxv[0] = x >> 1; wxv[0] = 1; nxc = 1; }
    else {
        mxv[nxc] = x >> 1; wxv[nxc] = 2; nxc++;
        if ((x >> 1) + 1 < GW1) { mxv[nxc] = (x >> 1) + 1; wxv[nxc] = 0; nxc++; }
    }

    float4 acc = make_float4(0.f, 0.f, 0.f, 0.f);
    for (int a = 0; a < nzc; a++)
        for (int b = 0; b < nyc; b++)
            for (int c = 0; c < nxc; c++) {
                int m = ((mzv[a] * GH1) + myv[b]) * GW1 + mxv[c];
                int tap = (wzv[a] * 3 + wyv[b]) * 3 + wxv[c];
                xs[g][t] = X[(size_t)m * CS + t];
                xs[g][t + 32] = X[(size_t)m * CS + t + 32];
                __syncwarp();
                dotrow4<CIN>(Wt + (tap * COUT + t) * CIN, xs[g], acc);
                __syncwarp();
            }
    out[(size_t)p * COUT + t] = acc.x + acc.y + acc.z + acc.w;
}

// ---------------- launch ----------------
extern "C" void kernel_launch(void* const* d_in, const int* in_sizes, int n_in,
                              void* d_out, int out_size) {
    const float* features = (const float*)d_in[0];
    const int* coors      = (const int*)d_in[1];
    int wb = n_in - 10;
    const float* w_sub0  = (const float*)d_in[wb + 0];
    const float* w_sub1  = (const float*)d_in[wb + 1];
    const float* w_sub2  = (const float*)d_in[wb + 2];
    const float* w_sub3  = (const float*)d_in[wb + 3];
    const float* w_down0 = (const float*)d_in[wb + 4];
    const float* w_sub4  = (const float*)d_in[wb + 5];
    const float* w_sub5  = (const float*)d_in[wb + 6];
    const float* w_down1 = (const float*)d_in[wb + 7];
    const float* w_inv1  = (const float*)d_in[wb + 8];
    const float* w_inv0  = (const float*)d_in[wb + 9];

    int n = in_sizes[0] / 3;

    float *fA, *cA, *c2p, *maskp, *pwi0;
    __nv_bfloat16 *fXh, *fXl, *fYh, *fYl, *cAh, *cAl, *cBh, *cBl;
    __nv_bfloat16 *b1h, *b1l, *b2h, *b2l, *b3h, *b3l, *bd0h, *bd0l, *b4h, *b4l, *b5h, *b5l;
    cudaGetSymbolAddress((void**)&fA, g_fineA);
    cudaGetSymbolAddress((void**)&cA, g_cA);
    cudaGetSymbolAddress((void**)&c2p, g_c2);
    cudaGetSymbolAddress((void**)&maskp, g_mask);
    cudaGetSymbolAddress((void**)&pwi0, g_wi0);
    cudaGetSymbolAddress((void**)&fXh, g_fXh);
    cudaGetSymbolAddress((void**)&fXl, g_fXl);
    cudaGetSymbolAddress((void**)&fYh, g_fYh);
    cudaGetSymbolAddress((void**)&fYl, g_fYl);
    cudaGetSymbolAddress((void**)&cAh, g_cAh);
    cudaGetSymbolAddress((void**)&cAl, g_cAl);
    cudaGetSymbolAddress((void**)&cBh, g_cBh);
    cudaGetSymbolAddress((void**)&cBl, g_cBl);
    cudaGetSymbolAddress((void**)&b1h, g_b1h);  cudaGetSymbolAddress((void**)&b1l, g_b1l);
    cudaGetSymbolAddress((void**)&b2h, g_b2h);  cudaGetSymbolAddress((void**)&b2l, g_b2l);
    cudaGetSymbolAddress((void**)&b3h, g_b3h);  cudaGetSymbolAddress((void**)&b3l, g_b3l);
    cudaGetSymbolAddress((void**)&bd0h, g_bd0h); cudaGetSymbolAddress((void**)&bd0l, g_bd0l);
    cudaGetSymbolAddress((void**)&b4h, g_b4h);  cudaGetSymbolAddress((void**)&b4l, g_b4l);
    cudaGetSymbolAddress((void**)&b5h, g_b5h);  cudaGetSymbolAddress((void**)&b5l, g_b5l);

    // dynamic smem sizes (max of mainloop and f32 out-tile reuse)
    constexpr int SM_F3232 = 2 * 128 * 40 * 2 + 2 * 32 * 40 * 2;                    // 25600
    constexpr int SM_F3264 = 256 * 64 * 4;                                           // out tile 65536
    constexpr int SM_F6464 = 2 * 256 * 72 * 2 + 2 * 64 * 72 * 2;                    // 92160
    constexpr int SM_D0    = 2 * 128 * 72 * 2 + 2 * 64 * 72 * 2;                    // 55296
    constexpr int SM_C64   = 2 * 128 * 72 * 2 + 2 * 64 * 104 * 2;                   // 63488
    constexpr int SM_C96   = 2 * 128 * 104 * 2 + 2 * 96 * 104 * 2;                  // 93184
    cudaFuncSetAttribute(conv_fine_wmma<32, 32, 128>, cudaFuncAttributeMaxDynamicSharedMemorySize, SM_F3232);
    cudaFuncSetAttribute(conv_fine_wmma<32, 64, 256>, cudaFuncAttributeMaxDynamicSharedMemorySize, SM_F3264);
    cudaFuncSetAttribute(conv_fine_wmma<64, 64, 256>, cudaFuncAttributeMaxDynamicSharedMemorySize, SM_F6464);
    cudaFuncSetAttribute(conv_down0_wmma, cudaFuncAttributeMaxDynamicSharedMemorySize, SM_D0);
    cudaFuncSetAttribute(conv_coarse_wmma<64, true>, cudaFuncAttributeMaxDynamicSharedMemorySize, SM_C64);
    cudaFuncSetAttribute(conv_coarse_wmma<96, false>, cudaFuncAttributeMaxDynamicSharedMemorySize, SM_C96);

    int nb128 = (n + 127) / 128;
    int nb256 = (n + 255) / 256;

    scatter_kernel<<<(n + 255) / 256, 256>>>(features, coors, fA, n);                         // 1
    bprep_kernel<<<(27 * 32 * 32 + 255) / 256, 256>>>(w_sub1, b1h, b1l, 27 * 32 * 32);        // 2
    conv_sub0_kernel<<<(n + 7) / 8, 256>>>(fA, fXh, fXl, coors, w_sub0, n);                   // 3
    // launch 4: PROFILED slot
    conv_fine_wmma<32, 32, 128><<<nb128, 256, SM_F3232>>>(fXh, fXl, fYh, fYl, coors, b1h, b1l, n); // 4
    bprep_kernel<<<(27 * 32 * 64 + 255) / 256, 256>>>(w_sub2, b2h, b2l, 27 * 32 * 64);        // 5
    conv_fine_wmma<32, 64, 256><<<nb256, 512, SM_F3264>>>(fYh, fYl, fXh, fXl, coors, b2h, b2l, n); // 6
    bprep_kernel<<<(27 * 64 * 64 + 255) / 256, 256>>>(w_sub3, b3h, b3l, 27 * 64 * 64);        // 7
    conv_fine_wmma<64, 64, 256><<<nb256, 512, SM_F6464>>>(fXh, fXl, fYh, fYl, coors, b3h, b3l, n); // 8
    mask_kernel<<<(n + 255) / 256, 256>>>(coors, maskp, n);                                   // 9
    bprep_kernel<<<(27 * 64 * 64 + 255) / 256, 256>>>(w_down0, bd0h, bd0l, 27 * 64 * 64);     // 10
    conv_down0_wmma<<<NC1 / 128, 256, SM_D0>>>(fYh, fYl, cAh, cAl, bd0h, bd0l);               // 11
    bprep_kernel<<<(27 * 64 * 96 + 255) / 256, 256>>>(w_sub4, b4h, b4l, 27 * 64 * 96);        // 12
    bprep_kernel<<<(27 * 96 * 96 + 255) / 256, 256>>>(w_sub5, b5h, b5l, 27 * 96 * 96);        // 13
    conv_coarse_wmma<64, true><<<NC1 / 128, 256, SM_C64>>>(cAh, cAl, nullptr, cBh, cBl,
                                                           b4h, b4l, maskp);                  // 14
    conv_coarse_wmma<96, false><<<NC1 / 128, 256, SM_C96>>>(cBh, cBl, cA, nullptr, nullptr,
                                                            b5h, b5l, maskp);                 // 15
    conv_down1_kernel<<<NC2 / 64, 192>>>(cA, c2p, w_down1);                                   // 16
    repack_kernel<<<(27 * 64 * 32 + 255) / 256, 256>>>(w_inv0, pwi0, 27, 64, 32);             // 17
    inv1_tiled_kernel<<<NC1 / 64, 128>>>(c2p, cA, w_inv1, maskp);                             // 18
    inv0_kernel<<<(n + 7) / 8, 256>>>(cA, (float*)d_out, coors, pwi0, n);                     // 19
}